// round 3
// baseline (speedup 1.0000x reference)
#include <cuda_runtime.h>
#include <math.h>

// Problem constants
static constexpr int BATCH = 32;
static constexpr int SEQ   = 512;
static constexpr int DIM   = 768;
static constexpr int HEADS = 12;
static constexpr int HDIM  = 64;
static constexpr int MROWS = BATCH * SEQ;   // 16384
static constexpr int DFF   = 3072;

// Scratch (device globals — allocation-free rule)
__device__ float g_h   [MROWS * DIM];   // LN1 out; later reused for attn out (BND layout)
__device__ float g_q   [MROWS * DIM];   // q in [B,H,N,HD]; later reused for h2
__device__ float g_k   [MROWS * DIM];
__device__ float g_v   [MROWS * DIM];
__device__ float g_out1[MROWS * DIM];   // attn block output (pre-FFN residual source)
__device__ float g_ffn [MROWS * DFF];

// ---------------------------------------------------------------------------
// LayerNorm: one block per row of 768, 256 threads
// ---------------------------------------------------------------------------
__global__ __launch_bounds__(256) void ln_kernel(
    const float* __restrict__ x, const float* __restrict__ g,
    const float* __restrict__ b, float* __restrict__ y)
{
    int row = blockIdx.x;
    int tid = threadIdx.x;
    const float* xr = x + (size_t)row * DIM;
    float v0 = xr[tid], v1 = xr[tid + 256], v2 = xr[tid + 512];
    float s  = v0 + v1 + v2;
    float ss = v0 * v0 + v1 * v1 + v2 * v2;
    #pragma unroll
    for (int o = 16; o > 0; o >>= 1) {
        s  += __shfl_xor_sync(0xffffffffu, s, o);
        ss += __shfl_xor_sync(0xffffffffu, ss, o);
    }
    __shared__ float sh_s[8], sh_ss[8];
    int w = tid >> 5, l = tid & 31;
    if (l == 0) { sh_s[w] = s; sh_ss[w] = ss; }
    __syncthreads();
    float ts = 0.f, tss = 0.f;
    #pragma unroll
    for (int i = 0; i < 8; i++) { ts += sh_s[i]; tss += sh_ss[i]; }
    float mean = ts * (1.0f / DIM);
    float var  = tss * (1.0f / DIM) - mean * mean;
    float inv  = rsqrtf(var + 1e-5f);
    float* yr = y + (size_t)row * DIM;
    yr[tid]       = (v0 - mean) * inv * g[tid]       + b[tid];
    yr[tid + 256] = (v1 - mean) * inv * g[tid + 256] + b[tid + 256];
    yr[tid + 512] = (v2 - mean) * inv * g[tid + 512] + b[tid + 512];
}

// ---------------------------------------------------------------------------
// fp32 SGEMM: C = A[M,K] @ B[K,N] (+epilogue). 128x128x16 tile, 8x8/thread.
// EPI 0: +bias, permuted store to [B,H,N,HD]
// EPI 1: +bias +res, normal store
// EPI 2: +bias, exact GELU, normal store
// ---------------------------------------------------------------------------
template <int EPI>
__global__ __launch_bounds__(256) void gemm_kernel(
    const float* __restrict__ A, const float* __restrict__ Bw,
    const float* __restrict__ bias, const float* __restrict__ res,
    float* __restrict__ C, int Nc, int K)
{
    __shared__ float As[16][132];   // transposed A tile, padded
    __shared__ float Bs[16][128];
    int tid = threadIdx.x;
    int ty = tid >> 4, tx = tid & 15;
    int row0 = blockIdx.y * 128;
    int col0 = blockIdx.x * 128;

    float acc[8][8];
    #pragma unroll
    for (int i = 0; i < 8; i++)
        #pragma unroll
        for (int j = 0; j < 8; j++) acc[i][j] = 0.f;

    const float* Ap = A + (size_t)row0 * K;
    const float* Bp = Bw + col0;

    for (int k0 = 0; k0 < K; k0 += 16) {
        #pragma unroll
        for (int it = 0; it < 2; it++) {
            int idx = tid + it * 256;
            int r = idx >> 2;            // 0..127
            int c = (idx & 3) << 2;      // 0,4,8,12
            float4 av = *(const float4*)(Ap + (size_t)r * K + k0 + c);
            As[c + 0][r] = av.x; As[c + 1][r] = av.y;
            As[c + 2][r] = av.z; As[c + 3][r] = av.w;
        }
        #pragma unroll
        for (int it = 0; it < 2; it++) {
            int idx = tid + it * 256;
            int r = idx >> 5;            // 0..15
            int c = (idx & 31) << 2;     // 0..124
            *(float4*)(&Bs[r][c]) = *(const float4*)(Bp + (size_t)(k0 + r) * Nc + c);
        }
        __syncthreads();
        #pragma unroll
        for (int k = 0; k < 16; k++) {
            float a[8], bb[8];
            *(float4*)&a[0]  = *(float4*)&As[k][ty * 8];
            *(float4*)&a[4]  = *(float4*)&As[k][ty * 8 + 4];
            *(float4*)&bb[0] = *(float4*)&Bs[k][tx * 8];
            *(float4*)&bb[4] = *(float4*)&Bs[k][tx * 8 + 4];
            #pragma unroll
            for (int i = 0; i < 8; i++)
                #pragma unroll
                for (int j = 0; j < 8; j++)
                    acc[i][j] += a[i] * bb[j];
        }
        __syncthreads();
    }

    #pragma unroll
    for (int i = 0; i < 8; i++) {
        int m = row0 + ty * 8 + i;
        #pragma unroll
        for (int j = 0; j < 8; j++) {
            int c = col0 + tx * 8 + j;
            float v = acc[i][j] + bias[c];
            if (EPI == 0) {
                int b = m >> 9, n = m & 511;
                int h = c >> 6, d = c & 63;
                C[(((size_t)(b * HEADS + h)) * SEQ + n) * HDIM + d] = v;
            } else if (EPI == 1) {
                C[(size_t)m * Nc + c] = v + res[(size_t)m * Nc + c];
            } else {
                C[(size_t)m * Nc + c] = 0.5f * v * (1.0f + erff(v * 0.70710678118654752f));
            }
        }
    }
}

// ---------------------------------------------------------------------------
// Masked attention: grid (SEQ/64, B*H), 256 threads. Scores in smem.
// Writes output directly in [B, N, 768] layout.
// ---------------------------------------------------------------------------
__global__ __launch_bounds__(256) void attn_kernel(
    const float* __restrict__ q, const float* __restrict__ kin,
    const float* __restrict__ v, const int* __restrict__ adj,
    float* __restrict__ out)
{
    extern __shared__ float sm[];
    float* sq  = sm;                 // 64*64   (q natural)
    float* skv = sm + 4096;          // 64*65   (K transposed / V natural)
    float* ss  = sm + 4096 + 4160;   // 64*512  (scores / probs)

    int tid = threadIdx.x;
    int ty = tid >> 4, tx = tid & 15;
    int bh = blockIdx.y;
    int b = bh / HEADS, h = bh % HEADS;
    int q0 = blockIdx.x * 64;

    const float* qb = q   + (size_t)bh * SEQ * HDIM + (size_t)q0 * HDIM;
    const float* kb = kin + (size_t)bh * SEQ * HDIM;
    const float* vb = v   + (size_t)bh * SEQ * HDIM;

    // Load Q tile (natural layout, stride 64)
    #pragma unroll
    for (int it = 0; it < 4; it++) {
        int idx = tid + it * 256;
        int r = idx >> 4;
        int c = (idx & 15) << 2;
        *(float4*)(sq + r * 64 + c) = *(const float4*)(qb + (size_t)r * HDIM + c);
    }

    const float scale = 0.125f;  // 64^-0.5

    // ---- Phase 1: scores = mask(scale * Q K^T) into smem ----
    for (int kt = 0; kt < 8; kt++) {
        #pragma unroll
        for (int it = 0; it < 4; it++) {
            int idx = tid + it * 256;
            int r = idx >> 4;                 // key row in tile
            int c = (idx & 15) << 2;          // d0
            float4 k4 = *(const float4*)(kb + (size_t)(kt * 64 + r) * HDIM + c);
            skv[(c + 0) * 65 + r] = k4.x;
            skv[(c + 1) * 65 + r] = k4.y;
            skv[(c + 2) * 65 + r] = k4.z;
            skv[(c + 3) * 65 + r] = k4.w;
        }
        __syncthreads();

        float acc[4][4];
        #pragma unroll
        for (int i = 0; i < 4; i++)
            #pragma unroll
            for (int j = 0; j < 4; j++) acc[i][j] = 0.f;

        #pragma unroll 16
        for (int d = 0; d < 64; d++) {
            float a[4], bb[4];
            #pragma unroll
            for (int i = 0; i < 4; i++) a[i] = sq[(ty * 4 + i) * 64 + d];
            #pragma unroll
            for (int j = 0; j < 4; j++) bb[j] = skv[d * 65 + tx * 4 + j];
            #pragma unroll
            for (int i = 0; i < 4; i++)
                #pragma unroll
                for (int j = 0; j < 4; j++)
                    acc[i][j] += a[i] * bb[j];
        }

        #pragma unroll
        for (int i = 0; i < 4; i++) {
            int qi = ty * 4 + i;
            const int* arow = adj + ((size_t)b * SEQ + q0 + qi) * SEQ + kt * 64 + tx * 4;
            #pragma unroll
            for (int j = 0; j < 4; j++) {
                float s = acc[i][j] * scale;
                if (arow[j] == 0) s = -1e30f;
                ss[qi * 512 + kt * 64 + tx * 4 + j] = s;
            }
        }
        __syncthreads();
    }

    // ---- Phase 2: softmax, warp per row (8 warps x 8 rows) ----
    int w = tid >> 5, l = tid & 31;
    for (int rr = 0; rr < 8; rr++) {
        int qi = w * 8 + rr;
        float* row = ss + qi * 512;
        float mx = -1e30f;
        #pragma unroll
        for (int i = 0; i < 16; i++) mx = fmaxf(mx, row[l + i * 32]);
        #pragma unroll
        for (int o = 16; o > 0; o >>= 1) mx = fmaxf(mx, __shfl_xor_sync(0xffffffffu, mx, o));
        float e[16], sum = 0.f;
        #pragma unroll
        for (int i = 0; i < 16; i++) { e[i] = __expf(row[l + i * 32] - mx); sum += e[i]; }
        #pragma unroll
        for (int o = 16; o > 0; o >>= 1) sum += __shfl_xor_sync(0xffffffffu, sum, o);
        float inv = 1.0f / sum;
        #pragma unroll
        for (int i = 0; i < 16; i++) row[l + i * 32] = e[i] * inv;
    }
    __syncthreads();

    // ---- Phase 3: out = P @ V ----
    float acc2[4][4];
    #pragma unroll
    for (int i = 0; i < 4; i++)
        #pragma unroll
        for (int j = 0; j < 4; j++) acc2[i][j] = 0.f;

    for (int kt = 0; kt < 8; kt++) {
        #pragma unroll
        for (int it = 0; it < 4; it++) {
            int idx = tid + it * 256;
            int r = idx >> 4;
            int c = (idx & 15) << 2;
            *(float4*)(skv + r * 64 + c) =
                *(const float4*)(vb + (size_t)(kt * 64 + r) * HDIM + c);
        }
        __syncthreads();
        #pragma unroll 8
        for (int kj = 0; kj < 64; kj++) {
            float a[4];
            #pragma unroll
            for (int i = 0; i < 4; i++) a[i] = ss[(ty * 4 + i) * 512 + kt * 64 + kj];
            float4 b4 = *(float4*)(skv + kj * 64 + tx * 4);
            #pragma unroll
            for (int i = 0; i < 4; i++) {
                acc2[i][0] += a[i] * b4.x;
                acc2[i][1] += a[i] * b4.y;
                acc2[i][2] += a[i] * b4.z;
                acc2[i][3] += a[i] * b4.w;
            }
        }
        __syncthreads();
    }

    // Store directly in [B, N, DIM] layout
    #pragma unroll
    for (int i = 0; i < 4; i++) {
        int qi = ty * 4 + i;
        float4 o4 = make_float4(acc2[i][0], acc2[i][1], acc2[i][2], acc2[i][3]);
        *(float4*)(out + ((size_t)(b * SEQ) + q0 + qi) * DIM + h * HDIM + tx * 4) = o4;
    }
}

// ---------------------------------------------------------------------------
extern "C" void kernel_launch(void* const* d_in, const int* in_sizes, int n_in,
                              void* d_out, int out_size)
{
    const float* x   = (const float*)d_in[0];
    const int*   adj = (const int*)  d_in[1];
    const float* wq  = (const float*)d_in[2];
    const float* bq  = (const float*)d_in[3];
    const float* wk  = (const float*)d_in[4];
    const float* bk  = (const float*)d_in[5];
    const float* wv  = (const float*)d_in[6];
    const float* bv  = (const float*)d_in[7];
    const float* wo  = (const float*)d_in[8];
    const float* bo  = (const float*)d_in[9];
    const float* g1  = (const float*)d_in[10];
    const float* b1  = (const float*)d_in[11];
    const float* g2  = (const float*)d_in[12];
    const float* b2  = (const float*)d_in[13];
    const float* w1  = (const float*)d_in[14];
    const float* bf1 = (const float*)d_in[15];
    const float* w2  = (const float*)d_in[16];
    const float* bf2 = (const float*)d_in[17];
    float* out = (float*)d_out;

    float *ph, *pq, *pk, *pv, *pout1, *pffn;
    cudaGetSymbolAddress((void**)&ph,    g_h);
    cudaGetSymbolAddress((void**)&pq,    g_q);
    cudaGetSymbolAddress((void**)&pk,    g_k);
    cudaGetSymbolAddress((void**)&pv,    g_v);
    cudaGetSymbolAddress((void**)&pout1, g_out1);
    cudaGetSymbolAddress((void**)&pffn,  g_ffn);

    // 1. LN1
    ln_kernel<<<MROWS, 256>>>(x, g1, b1, ph);

    // 2-4. QKV projections (permuted epilogue into [B,H,N,HD])
    dim3 g768(DIM / 128, MROWS / 128);
    gemm_kernel<0><<<g768, 256>>>(ph, wq, bq, nullptr, pq, DIM, DIM);
    gemm_kernel<0><<<g768, 256>>>(ph, wk, bk, nullptr, pk, DIM, DIM);
    gemm_kernel<0><<<g768, 256>>>(ph, wv, bv, nullptr, pv, DIM, DIM);

    // 5. Masked attention (writes [B,N,DIM] into g_h, which is free now)
    int smem = (4096 + 4160 + 64 * 512) * 4;  // 164096 B
    cudaFuncSetAttribute(attn_kernel, cudaFuncAttributeMaxDynamicSharedMemorySize, smem);
    attn_kernel<<<dim3(SEQ / 64, BATCH * HEADS), 256, smem>>>(pq, pk, pv, adj, ph);

    // 6. Output projection + bias + residual(x)
    gemm_kernel<1><<<g768, 256>>>(ph, wo, bo, x, pout1, DIM, DIM);

    // 7. LN2 (h2 into g_q, free now)
    ln_kernel<<<MROWS, 256>>>(pout1, g2, b2, pq);

    // 8. FFN1 + GELU
    dim3 g3072(DFF / 128, MROWS / 128);
    gemm_kernel<2><<<g3072, 256>>>(pq, w1, bf1, nullptr, pffn, DFF, DIM);

    // 9. FFN2 + bias + residual(out1) -> final output
    gemm_kernel<1><<<g768, 256>>>(pffn, w2, bf2, pout1, out, DIM, DFF);
}

// round 5
// speedup vs baseline: 2.0807x; 2.0807x over previous
#include <cuda_runtime.h>
#include <math.h>
#include <stdint.h>

// Problem constants
static constexpr int BATCH = 32;
static constexpr int SEQ   = 512;
static constexpr int DIM   = 768;
static constexpr int HEADS = 12;
static constexpr int HDIM  = 64;
static constexpr int MROWS = BATCH * SEQ;   // 16384
static constexpr int DFF   = 3072;

// Scratch (device globals — allocation-free rule)
__device__ float g_h   [MROWS * DIM];
__device__ float g_q   [MROWS * DIM];
__device__ float g_k   [MROWS * DIM];
__device__ float g_v   [MROWS * DIM];
__device__ float g_out1[MROWS * DIM];
__device__ float g_ffn [MROWS * DFF];

// ---------------------------------------------------------------------------
// Helpers
// ---------------------------------------------------------------------------
__device__ __forceinline__ float f2tf32f(float x) {
    uint32_t r; asm("cvt.rna.tf32.f32 %0, %1;" : "=r"(r) : "f"(x));
    return __uint_as_float(r);
}
__device__ __forceinline__ void mma_tf32(float* c, const uint32_t* a, const uint32_t* b) {
    asm volatile(
        "mma.sync.aligned.m16n8k8.row.col.f32.tf32.tf32.f32 "
        "{%0,%1,%2,%3}, {%4,%5,%6,%7}, {%8,%9}, {%0,%1,%2,%3};"
        : "+f"(c[0]), "+f"(c[1]), "+f"(c[2]), "+f"(c[3])
        : "r"(a[0]), "r"(a[1]), "r"(a[2]), "r"(a[3]), "r"(b[0]), "r"(b[1]));
}

// ---------------------------------------------------------------------------
// tf32 mma.sync GEMM: C[M,Nc] = A[M,K] @ W[K,Nc] (+epilogue)
// CTA 128x128, 8 warps (4x2), warp tile 32x64, K-stage 16 double buffered.
// EPI 0: +bias, permuted store to [B,H,N,HD]
// EPI 1: +bias +res
// EPI 2: +bias, exact GELU
// ---------------------------------------------------------------------------
template <int EPI>
__global__ __launch_bounds__(256, 2) void mma_gemm(
    const float* __restrict__ A, const float* __restrict__ W,
    const float* __restrict__ bias, const float* __restrict__ res,
    float* __restrict__ C, int Nc, int K)
{
    __shared__ float smA[2][128][20];   // row-major A tile, pad 20 (conflict-free frags)
    __shared__ float smB[2][16][136];   // k-major B tile, pad 136 (conflict-free frags)

    const int tid  = threadIdx.x;
    const int wid  = tid >> 5, lane = tid & 31;
    const int grp  = lane >> 2, tid4 = lane & 3;
    const int wm   = (wid >> 1) * 32;       // warp row offset in tile
    const int wn   = (wid & 1) * 64;        // warp col offset in tile
    const int row0 = blockIdx.y * 128;
    const int col0 = blockIdx.x * 128;

    // Loader indices (512 float4 per operand per stage; 2 iters of 256 threads)
    const int am  = tid >> 2;          // A row 0..63 (+64 on it=1 via idx)
    const int akq = tid & 3;           // A k-quad
    const int bk  = tid >> 5;          // B k row 0..7 (+8 on it=1)
    const int bn4 = (tid & 31) * 4;    // B col quad

    float acc[2][8][4];
    #pragma unroll
    for (int t = 0; t < 2; t++)
        #pragma unroll
        for (int j = 0; j < 8; j++)
            #pragma unroll
            for (int r = 0; r < 4; r++) acc[t][j][r] = 0.f;

    const int nst = K >> 4;

    // Prologue: stage 0 -> buffer 0
    #pragma unroll
    for (int it = 0; it < 2; it++) {
        int m = am + it * 64;
        float4 v = *(const float4*)(A + (size_t)(row0 + m) * K + akq * 4);
        smA[0][m][akq * 4 + 0] = f2tf32f(v.x);
        smA[0][m][akq * 4 + 1] = f2tf32f(v.y);
        smA[0][m][akq * 4 + 2] = f2tf32f(v.z);
        smA[0][m][akq * 4 + 3] = f2tf32f(v.w);
        int k = bk + it * 8;
        float4 w4 = *(const float4*)(W + (size_t)k * Nc + col0 + bn4);
        smB[0][k][bn4 + 0] = f2tf32f(w4.x);
        smB[0][k][bn4 + 1] = f2tf32f(w4.y);
        smB[0][k][bn4 + 2] = f2tf32f(w4.z);
        smB[0][k][bn4 + 3] = f2tf32f(w4.w);
    }
    __syncthreads();

    for (int st = 0; st < nst; st++) {
        const int bf = st & 1;
        float4 ra[2], rb[2];
        const bool more = (st + 1 < nst);
        if (more) {
            const int k0 = (st + 1) << 4;
            #pragma unroll
            for (int it = 0; it < 2; it++) {
                int m = am + it * 64;
                ra[it] = *(const float4*)(A + (size_t)(row0 + m) * K + k0 + akq * 4);
                int k = bk + it * 8;
                rb[it] = *(const float4*)(W + (size_t)(k0 + k) * Nc + col0 + bn4);
            }
        }

        // Compute stage st: two k8 sub-steps
        #pragma unroll
        for (int s = 0; s < 2; s++) {
            uint32_t af[2][4];
            #pragma unroll
            for (int t = 0; t < 2; t++) {
                int r = wm + t * 16 + grp;
                af[t][0] = __float_as_uint(smA[bf][r    ][s * 8 + tid4    ]);
                af[t][1] = __float_as_uint(smA[bf][r + 8][s * 8 + tid4    ]);
                af[t][2] = __float_as_uint(smA[bf][r    ][s * 8 + tid4 + 4]);
                af[t][3] = __float_as_uint(smA[bf][r + 8][s * 8 + tid4 + 4]);
            }
            uint32_t bfr[8][2];
            #pragma unroll
            for (int j = 0; j < 8; j++) {
                int c = wn + j * 8 + grp;
                bfr[j][0] = __float_as_uint(smB[bf][s * 8 + tid4    ][c]);
                bfr[j][1] = __float_as_uint(smB[bf][s * 8 + tid4 + 4][c]);
            }
            #pragma unroll
            for (int t = 0; t < 2; t++)
                #pragma unroll
                for (int j = 0; j < 8; j++)
                    mma_tf32(acc[t][j], af[t], bfr[j]);
        }

        if (more) {
            const int nb = bf ^ 1;
            #pragma unroll
            for (int it = 0; it < 2; it++) {
                int m = am + it * 64;
                smA[nb][m][akq * 4 + 0] = f2tf32f(ra[it].x);
                smA[nb][m][akq * 4 + 1] = f2tf32f(ra[it].y);
                smA[nb][m][akq * 4 + 2] = f2tf32f(ra[it].z);
                smA[nb][m][akq * 4 + 3] = f2tf32f(ra[it].w);
                int k = bk + it * 8;
                smB[nb][k][bn4 + 0] = f2tf32f(rb[it].x);
                smB[nb][k][bn4 + 1] = f2tf32f(rb[it].y);
                smB[nb][k][bn4 + 2] = f2tf32f(rb[it].z);
                smB[nb][k][bn4 + 3] = f2tf32f(rb[it].w);
            }
        }
        __syncthreads();
    }

    // Epilogue: fused bias / residual / GELU / QKV permute; float2 stores
    #pragma unroll
    for (int t = 0; t < 2; t++) {
        int r_lo = row0 + wm + t * 16 + grp;
        int r_hi = r_lo + 8;
        #pragma unroll
        for (int j = 0; j < 8; j++) {
            int c = col0 + wn + j * 8 + tid4 * 2;
            float b0 = bias[c], b1 = bias[c + 1];
            float v00 = acc[t][j][0] + b0, v01 = acc[t][j][1] + b1;
            float v10 = acc[t][j][2] + b0, v11 = acc[t][j][3] + b1;
            if (EPI == 0) {
                int h = c >> 6, d = c & 63;
                int blo = r_lo >> 9, nlo = r_lo & 511;
                int bhi = r_hi >> 9, nhi = r_hi & 511;
                *(float2*)(C + (((size_t)(blo * HEADS + h)) * SEQ + nlo) * HDIM + d) =
                    make_float2(v00, v01);
                *(float2*)(C + (((size_t)(bhi * HEADS + h)) * SEQ + nhi) * HDIM + d) =
                    make_float2(v10, v11);
            } else if (EPI == 1) {
                const float2 r0 = *(const float2*)(res + (size_t)r_lo * Nc + c);
                const float2 r1 = *(const float2*)(res + (size_t)r_hi * Nc + c);
                *(float2*)(C + (size_t)r_lo * Nc + c) = make_float2(v00 + r0.x, v01 + r0.y);
                *(float2*)(C + (size_t)r_hi * Nc + c) = make_float2(v10 + r1.x, v11 + r1.y);
            } else {
                const float inv_sqrt2 = 0.70710678118654752f;
                v00 = 0.5f * v00 * (1.0f + erff(v00 * inv_sqrt2));
                v01 = 0.5f * v01 * (1.0f + erff(v01 * inv_sqrt2));
                v10 = 0.5f * v10 * (1.0f + erff(v10 * inv_sqrt2));
                v11 = 0.5f * v11 * (1.0f + erff(v11 * inv_sqrt2));
                *(float2*)(C + (size_t)r_lo * Nc + c) = make_float2(v00, v01);
                *(float2*)(C + (size_t)r_hi * Nc + c) = make_float2(v10, v11);
            }
        }
    }
}

// ---------------------------------------------------------------------------
// LayerNorm: one block per row of 768, 256 threads
// ---------------------------------------------------------------------------
__global__ __launch_bounds__(256) void ln_kernel(
    const float* __restrict__ x, const float* __restrict__ g,
    const float* __restrict__ b, float* __restrict__ y)
{
    int row = blockIdx.x;
    int tid = threadIdx.x;
    const float* xr = x + (size_t)row * DIM;
    float v0 = xr[tid], v1 = xr[tid + 256], v2 = xr[tid + 512];
    float s  = v0 + v1 + v2;
    float ss = v0 * v0 + v1 * v1 + v2 * v2;
    #pragma unroll
    for (int o = 16; o > 0; o >>= 1) {
        s  += __shfl_xor_sync(0xffffffffu, s, o);
        ss += __shfl_xor_sync(0xffffffffu, ss, o);
    }
    __shared__ float sh_s[8], sh_ss[8];
    int w = tid >> 5, l = tid & 31;
    if (l == 0) { sh_s[w] = s; sh_ss[w] = ss; }
    __syncthreads();
    float ts = 0.f, tss = 0.f;
    #pragma unroll
    for (int i = 0; i < 8; i++) { ts += sh_s[i]; tss += sh_ss[i]; }
    float mean = ts * (1.0f / DIM);
    float var  = tss * (1.0f / DIM) - mean * mean;
    float inv  = rsqrtf(var + 1e-5f);
    float* yr = y + (size_t)row * DIM;
    yr[tid]       = (v0 - mean) * inv * g[tid]       + b[tid];
    yr[tid + 256] = (v1 - mean) * inv * g[tid + 256] + b[tid + 256];
    yr[tid + 512] = (v2 - mean) * inv * g[tid + 512] + b[tid + 512];
}

// ---------------------------------------------------------------------------
// Masked attention (fp32): grid (SEQ/64, B*H), 256 threads. Scores in smem.
// ---------------------------------------------------------------------------
__global__ __launch_bounds__(256) void attn_kernel(
    const float* __restrict__ q, const float* __restrict__ kin,
    const float* __restrict__ v, const int* __restrict__ adj,
    float* __restrict__ out)
{
    extern __shared__ float sm[];
    float* sq  = sm;                 // 64*64
    float* skv = sm + 4096;          // 64*65
    float* ss  = sm + 4096 + 4160;   // 64*512

    int tid = threadIdx.x;
    int ty = tid >> 4, tx = tid & 15;
    int bh = blockIdx.y;
    int b = bh / HEADS, h = bh % HEADS;
    int q0 = blockIdx.x * 64;

    const float* qb = q   + (size_t)bh * SEQ * HDIM + (size_t)q0 * HDIM;
    const float* kb = kin + (size_t)bh * SEQ * HDIM;
    const float* vb = v   + (size_t)bh * SEQ * HDIM;

    #pragma unroll
    for (int it = 0; it < 4; it++) {
        int idx = tid + it * 256;
        int r = idx >> 4;
        int c = (idx & 15) << 2;
        *(float4*)(sq + r * 64 + c) = *(const float4*)(qb + (size_t)r * HDIM + c);
    }

    const float scale = 0.125f;

    for (int kt = 0; kt < 8; kt++) {
        #pragma unroll
        for (int it = 0; it < 4; it++) {
            int idx = tid + it * 256;
            int r = idx >> 4;
            int c = (idx & 15) << 2;
            float4 k4 = *(const float4*)(kb + (size_t)(kt * 64 + r) * HDIM + c);
            skv[(c + 0) * 65 + r] = k4.x;
            skv[(c + 1) * 65 + r] = k4.y;
            skv[(c + 2) * 65 + r] = k4.z;
            skv[(c + 3) * 65 + r] = k4.w;
        }
        __syncthreads();

        float acc[4][4];
        #pragma unroll
        for (int i = 0; i < 4; i++)
            #pragma unroll
            for (int j = 0; j < 4; j++) acc[i][j] = 0.f;

        #pragma unroll 16
        for (int d = 0; d < 64; d++) {
            float a[4], bb[4];
            #pragma unroll
            for (int i = 0; i < 4; i++) a[i] = sq[(ty * 4 + i) * 64 + d];
            #pragma unroll
            for (int j = 0; j < 4; j++) bb[j] = skv[d * 65 + tx * 4 + j];
            #pragma unroll
            for (int i = 0; i < 4; i++)
                #pragma unroll
                for (int j = 0; j < 4; j++)
                    acc[i][j] += a[i] * bb[j];
        }

        #pragma unroll
        for (int i = 0; i < 4; i++) {
            int qi = ty * 4 + i;
            const int* arow = adj + ((size_t)b * SEQ + q0 + qi) * SEQ + kt * 64 + tx * 4;
            #pragma unroll
            for (int j = 0; j < 4; j++) {
                float s = acc[i][j] * scale;
                if (arow[j] == 0) s = -1e30f;
                ss[qi * 512 + kt * 64 + tx * 4 + j] = s;
            }
        }
        __syncthreads();
    }

    int w = tid >> 5, l = tid & 31;
    for (int rr = 0; rr < 8; rr++) {
        int qi = w * 8 + rr;
        float* row = ss + qi * 512;
        float mx = -1e30f;
        #pragma unroll
        for (int i = 0; i < 16; i++) mx = fmaxf(mx, row[l + i * 32]);
        #pragma unroll
        for (int o = 16; o > 0; o >>= 1) mx = fmaxf(mx, __shfl_xor_sync(0xffffffffu, mx, o));
        float e[16], sum = 0.f;
        #pragma unroll
        for (int i = 0; i < 16; i++) { e[i] = __expf(row[l + i * 32] - mx); sum += e[i]; }
        #pragma unroll
        for (int o = 16; o > 0; o >>= 1) sum += __shfl_xor_sync(0xffffffffu, sum, o);
        float inv = 1.0f / sum;
        #pragma unroll
        for (int i = 0; i < 16; i++) row[l + i * 32] = e[i] * inv;
    }
    __syncthreads();

    float acc2[4][4];
    #pragma unroll
    for (int i = 0; i < 4; i++)
        #pragma unroll
        for (int j = 0; j < 4; j++) acc2[i][j] = 0.f;

    for (int kt = 0; kt < 8; kt++) {
        #pragma unroll
        for (int it = 0; it < 4; it++) {
            int idx = tid + it * 256;
            int r = idx >> 4;
            int c = (idx & 15) << 2;
            *(float4*)(skv + r * 64 + c) =
                *(const float4*)(vb + (size_t)(kt * 64 + r) * HDIM + c);
        }
        __syncthreads();
        #pragma unroll 8
        for (int kj = 0; kj < 64; kj++) {
            float a[4];
            #pragma unroll
            for (int i = 0; i < 4; i++) a[i] = ss[(ty * 4 + i) * 512 + kt * 64 + kj];
            float4 b4 = *(float4*)(skv + kj * 64 + tx * 4);
            #pragma unroll
            for (int i = 0; i < 4; i++) {
                acc2[i][0] += a[i] * b4.x;
                acc2[i][1] += a[i] * b4.y;
                acc2[i][2] += a[i] * b4.z;
                acc2[i][3] += a[i] * b4.w;
            }
        }
        __syncthreads();
    }

    #pragma unroll
    for (int i = 0; i < 4; i++) {
        int qi = ty * 4 + i;
        float4 o4 = make_float4(acc2[i][0], acc2[i][1], acc2[i][2], acc2[i][3]);
        *(float4*)(out + ((size_t)(b * SEQ) + q0 + qi) * DIM + h * HDIM + tx * 4) = o4;
    }
}

// ---------------------------------------------------------------------------
extern "C" void kernel_launch(void* const* d_in, const int* in_sizes, int n_in,
                              void* d_out, int out_size)
{
    const float* x   = (const float*)d_in[0];
    const int*   adj = (const int*)  d_in[1];
    const float* wq  = (const float*)d_in[2];
    const float* bq  = (const float*)d_in[3];
    const float* wk  = (const float*)d_in[4];
    const float* bk  = (const float*)d_in[5];
    const float* wv  = (const float*)d_in[6];
    const float* bv  = (const float*)d_in[7];
    const float* wo  = (const float*)d_in[8];
    const float* bo  = (const float*)d_in[9];
    const float* g1  = (const float*)d_in[10];
    const float* b1  = (const float*)d_in[11];
    const float* g2  = (const float*)d_in[12];
    const float* b2  = (const float*)d_in[13];
    const float* w1  = (const float*)d_in[14];
    const float* bf1 = (const float*)d_in[15];
    const float* w2  = (const float*)d_in[16];
    const float* bf2 = (const float*)d_in[17];
    float* out = (float*)d_out;

    float *ph, *pq, *pk, *pv, *pout1, *pffn;
    cudaGetSymbolAddress((void**)&ph,    g_h);
    cudaGetSymbolAddress((void**)&pq,    g_q);
    cudaGetSymbolAddress((void**)&pk,    g_k);
    cudaGetSymbolAddress((void**)&pv,    g_v);
    cudaGetSymbolAddress((void**)&pout1, g_out1);
    cudaGetSymbolAddress((void**)&pffn,  g_ffn);

    static bool attr_set = false;
    if (!attr_set) {
        cudaFuncSetAttribute(attn_kernel, cudaFuncAttributeMaxDynamicSharedMemorySize,
                             (4096 + 4160 + 64 * 512) * 4);
        attr_set = true;
    }

    // 1. LN1
    ln_kernel<<<MROWS, 256>>>(x, g1, b1, ph);

    // 2-4. QKV projections (tf32 mma.sync, permuted epilogue into [B,H,N,HD])
    dim3 g768(DIM / 128, MROWS / 128);
    mma_gemm<0><<<g768, 256>>>(ph, wq, bq, nullptr, pq, DIM, DIM);
    mma_gemm<0><<<g768, 256>>>(ph, wk, bk, nullptr, pk, DIM, DIM);
    mma_gemm<0><<<g768, 256>>>(ph, wv, bv, nullptr, pv, DIM, DIM);

    // 5. Masked attention (writes [B,N,DIM] into g_h)
    int smem = (4096 + 4160 + 64 * 512) * 4;
    attn_kernel<<<dim3(SEQ / 64, BATCH * HEADS), 256, smem>>>(pq, pk, pv, adj, ph);

    // 6. Output projection + bias + residual(x)
    mma_gemm<1><<<g768, 256>>>(ph, wo, bo, x, pout1, DIM, DIM);

    // 7. LN2
    ln_kernel<<<MROWS, 256>>>(pout1, g2, b2, pq);

    // 8. FFN1 + GELU
    dim3 g3072(DFF / 128, MROWS / 128);
    mma_gemm<2><<<g3072, 256>>>(pq, w1, bf1, nullptr, pffn, DFF, DIM);

    // 9. FFN2 + bias + residual(out1) -> final output
    mma_gemm<1><<<g768, 256>>>(pffn, w2, bf2, pout1, out, DIM, DFF);
}

// round 6
// speedup vs baseline: 2.9517x; 1.4186x over previous
#include <cuda_runtime.h>
#include <math.h>
#include <stdint.h>

// Problem constants
static constexpr int BATCH = 32;
static constexpr int SEQ   = 512;
static constexpr int DIM   = 768;
static constexpr int HEADS = 12;
static constexpr int HDIM  = 64;
static constexpr int MROWS = BATCH * SEQ;   // 16384
static constexpr int DFF   = 3072;

// Scratch (device globals — allocation-free rule)
__device__ float g_h   [MROWS * DIM];
__device__ float g_q   [MROWS * DIM];
__device__ float g_k   [MROWS * DIM];
__device__ float g_v   [MROWS * DIM];
__device__ float g_out1[MROWS * DIM];
__device__ float g_ffn [MROWS * DFF];
// tf32-rounded weights: wq,wk,wv,wo (768x768), w1 (768x3072), w2 (3072x768)
__device__ float g_wt  [4 * DIM * DIM + 2 * DIM * DFF];

// ---------------------------------------------------------------------------
// Helpers
// ---------------------------------------------------------------------------
__device__ __forceinline__ uint32_t smem_u32(const void* p) {
    uint32_t a;
    asm("{ .reg .u64 t; cvta.to.shared.u64 t, %1; cvt.u32.u64 %0, t; }" : "=r"(a) : "l"(p));
    return a;
}
__device__ __forceinline__ float f2tf32f(float x) {
    uint32_t r; asm("cvt.rna.tf32.f32 %0, %1;" : "=r"(r) : "f"(x));
    return __uint_as_float(r);
}
__device__ __forceinline__ void mma_tf32(float* c, const uint32_t* a, const uint32_t* b) {
    asm volatile(
        "mma.sync.aligned.m16n8k8.row.col.f32.tf32.tf32.f32 "
        "{%0,%1,%2,%3}, {%4,%5,%6,%7}, {%8,%9}, {%0,%1,%2,%3};"
        : "+f"(c[0]), "+f"(c[1]), "+f"(c[2]), "+f"(c[3])
        : "r"(a[0]), "r"(a[1]), "r"(a[2]), "r"(a[3]), "r"(b[0]), "r"(b[1]));
}
#define CP_ASYNC16(dst, src) \
    asm volatile("cp.async.cg.shared.global [%0], [%1], 16;" :: "r"(dst), "l"(src))
#define CP_COMMIT()  asm volatile("cp.async.commit_group;" ::: "memory")
#define CP_WAIT(N)   asm volatile("cp.async.wait_group %0;" :: "n"(N) : "memory")

// ---------------------------------------------------------------------------
// Round weights to tf32
// ---------------------------------------------------------------------------
__global__ __launch_bounds__(256) void round_kernel(
    const float* __restrict__ src, float* __restrict__ dst, int n)
{
    int i = (blockIdx.x * 256 + threadIdx.x) * 4;
    if (i < n) {
        float4 v = *(const float4*)(src + i);
        *(float4*)(dst + i) = make_float4(f2tf32f(v.x), f2tf32f(v.y),
                                          f2tf32f(v.z), f2tf32f(v.w));
    }
}

// ---------------------------------------------------------------------------
// tf32 mma.sync GEMM, cp.async 4-stage pipeline.
// C[M,Nc] = A[M,K] @ W[K,Nc] (+epilogue). A and W pre-rounded to tf32.
// CTA 128x128, 8 warps (4x2), warp tile 32x64, K-stage 16.
// EPI 0: +bias, permuted+rounded store to [B,H,N,HD] (feeds attention)
// EPI 1: +bias +res (fp32 exact)
// EPI 2: +bias, exact GELU, rounded (feeds next GEMM)
// ---------------------------------------------------------------------------
static constexpr int GSTAGES = 4;
static constexpr int GEMM_SMEM = GSTAGES * (128 * 20 + 16 * 136) * 4;  // 75776 B

template <int EPI>
__global__ __launch_bounds__(256, 2) void mma_gemm(
    const float* __restrict__ A, const float* __restrict__ W,
    const float* __restrict__ bias, const float* __restrict__ res,
    float* __restrict__ C, int Nc, int K)
{
    extern __shared__ float dsm[];
    float (*smA)[128][20] = (float (*)[128][20])dsm;
    float (*smB)[16][136] = (float (*)[16][136])(dsm + GSTAGES * 128 * 20);

    const int tid  = threadIdx.x;
    const int wid  = tid >> 5, lane = tid & 31;
    const int grp  = lane >> 2, tid4 = lane & 3;
    const int wm   = (wid >> 1) * 32;
    const int wn   = (wid & 1) * 64;
    const int row0 = blockIdx.y * 128;
    const int col0 = blockIdx.x * 128;

    // cp.async chunk indices (2 x 16B per operand per thread per stage)
    const int am  = tid >> 2;          // A row (+64 on it=1)
    const int akq = (tid & 3) << 2;    // A k offset
    const int bk  = tid >> 5;          // B k row (+8 on it=1)
    const int bn4 = (tid & 31) << 2;   // B col offset

    float acc[2][8][4];
    #pragma unroll
    for (int t = 0; t < 2; t++)
        #pragma unroll
        for (int j = 0; j < 8; j++)
            #pragma unroll
            for (int r = 0; r < 4; r++) acc[t][j][r] = 0.f;

    const int nst = K >> 4;

    // Stage issue: stage s -> buffer s & 3
    auto issue = [&](int s) {
        const int b = s & 3;
        const int k0 = s << 4;
        #pragma unroll
        for (int it = 0; it < 2; it++) {
            int m = am + it * 64;
            CP_ASYNC16(smem_u32(&smA[b][m][akq]),
                       A + (size_t)(row0 + m) * K + k0 + akq);
            int k = bk + it * 8;
            CP_ASYNC16(smem_u32(&smB[b][k][bn4]),
                       W + (size_t)(k0 + k) * Nc + col0 + bn4);
        }
    };

    // Prologue: 3 stages in flight
    issue(0); CP_COMMIT();
    issue(1); CP_COMMIT();
    issue(2); CP_COMMIT();

    for (int st = 0; st < nst; st++) {
        CP_WAIT(2);
        __syncthreads();
        if (st + 3 < nst) issue(st + 3);
        CP_COMMIT();   // empty commit in tail keeps wait_group accounting valid

        const int bf = st & 3;
        #pragma unroll
        for (int s = 0; s < 2; s++) {
            uint32_t af[2][4];
            #pragma unroll
            for (int t = 0; t < 2; t++) {
                int r = wm + t * 16 + grp;
                af[t][0] = __float_as_uint(smA[bf][r    ][s * 8 + tid4    ]);
                af[t][1] = __float_as_uint(smA[bf][r + 8][s * 8 + tid4    ]);
                af[t][2] = __float_as_uint(smA[bf][r    ][s * 8 + tid4 + 4]);
                af[t][3] = __float_as_uint(smA[bf][r + 8][s * 8 + tid4 + 4]);
            }
            uint32_t bfr[8][2];
            #pragma unroll
            for (int j = 0; j < 8; j++) {
                int c = wn + j * 8 + grp;
                bfr[j][0] = __float_as_uint(smB[bf][s * 8 + tid4    ][c]);
                bfr[j][1] = __float_as_uint(smB[bf][s * 8 + tid4 + 4][c]);
            }
            #pragma unroll
            for (int t = 0; t < 2; t++)
                #pragma unroll
                for (int j = 0; j < 8; j++)
                    mma_tf32(acc[t][j], af[t], bfr[j]);
        }
        __syncthreads();
    }

    // Epilogue
    #pragma unroll
    for (int t = 0; t < 2; t++) {
        int r_lo = row0 + wm + t * 16 + grp;
        int r_hi = r_lo + 8;
        #pragma unroll
        for (int j = 0; j < 8; j++) {
            int c = col0 + wn + j * 8 + tid4 * 2;
            float b0 = bias[c], b1 = bias[c + 1];
            float v00 = acc[t][j][0] + b0, v01 = acc[t][j][1] + b1;
            float v10 = acc[t][j][2] + b0, v11 = acc[t][j][3] + b1;
            if (EPI == 0) {
                // rounded (consumed by tf32 attention)
                v00 = f2tf32f(v00); v01 = f2tf32f(v01);
                v10 = f2tf32f(v10); v11 = f2tf32f(v11);
                int h = c >> 6, d = c & 63;
                int blo = r_lo >> 9, nlo = r_lo & 511;
                int bhi = r_hi >> 9, nhi = r_hi & 511;
                *(float2*)(C + (((size_t)(blo * HEADS + h)) * SEQ + nlo) * HDIM + d) =
                    make_float2(v00, v01);
                *(float2*)(C + (((size_t)(bhi * HEADS + h)) * SEQ + nhi) * HDIM + d) =
                    make_float2(v10, v11);
            } else if (EPI == 1) {
                const float2 r0 = *(const float2*)(res + (size_t)r_lo * Nc + c);
                const float2 r1 = *(const float2*)(res + (size_t)r_hi * Nc + c);
                *(float2*)(C + (size_t)r_lo * Nc + c) = make_float2(v00 + r0.x, v01 + r0.y);
                *(float2*)(C + (size_t)r_hi * Nc + c) = make_float2(v10 + r1.x, v11 + r1.y);
            } else {
                const float is2 = 0.70710678118654752f;
                v00 = f2tf32f(0.5f * v00 * (1.0f + erff(v00 * is2)));
                v01 = f2tf32f(0.5f * v01 * (1.0f + erff(v01 * is2)));
                v10 = f2tf32f(0.5f * v10 * (1.0f + erff(v10 * is2)));
                v11 = f2tf32f(0.5f * v11 * (1.0f + erff(v11 * is2)));
                *(float2*)(C + (size_t)r_lo * Nc + c) = make_float2(v00, v01);
                *(float2*)(C + (size_t)r_hi * Nc + c) = make_float2(v10, v11);
            }
        }
    }
}

// ---------------------------------------------------------------------------
// LayerNorm: one block per row of 768; writes tf32-rounded (feeds GEMM A)
// ---------------------------------------------------------------------------
__global__ __launch_bounds__(256) void ln_kernel(
    const float* __restrict__ x, const float* __restrict__ g,
    const float* __restrict__ b, float* __restrict__ y)
{
    int row = blockIdx.x;
    int tid = threadIdx.x;
    const float* xr = x + (size_t)row * DIM;
    float v0 = xr[tid], v1 = xr[tid + 256], v2 = xr[tid + 512];
    float s  = v0 + v1 + v2;
    float ss = v0 * v0 + v1 * v1 + v2 * v2;
    #pragma unroll
    for (int o = 16; o > 0; o >>= 1) {
        s  += __shfl_xor_sync(0xffffffffu, s, o);
        ss += __shfl_xor_sync(0xffffffffu, ss, o);
    }
    __shared__ float sh_s[8], sh_ss[8];
    int w = tid >> 5, l = tid & 31;
    if (l == 0) { sh_s[w] = s; sh_ss[w] = ss; }
    __syncthreads();
    float ts = 0.f, tss = 0.f;
    #pragma unroll
    for (int i = 0; i < 8; i++) { ts += sh_s[i]; tss += sh_ss[i]; }
    float mean = ts * (1.0f / DIM);
    float var  = tss * (1.0f / DIM) - mean * mean;
    float inv  = rsqrtf(var + 1e-5f);
    float* yr = y + (size_t)row * DIM;
    yr[tid]       = f2tf32f((v0 - mean) * inv * g[tid]       + b[tid]);
    yr[tid + 256] = f2tf32f((v1 - mean) * inv * g[tid + 256] + b[tid + 256]);
    yr[tid + 512] = f2tf32f((v2 - mean) * inv * g[tid + 512] + b[tid + 512]);
}

// ---------------------------------------------------------------------------
// Masked attention on mma.sync tf32.
// Grid (SEQ/64, B*H), 256 threads (8 warps). Q/K/V pre-rounded tf32.
// Smem: sQ[64][68], sT[2][64][68] (K then V, double buffered), ss[64][516].
// Output written rounded to [B,N,768] (feeds wo GEMM).
// ---------------------------------------------------------------------------
static constexpr int APAD  = 68;
static constexpr int SPAD  = 516;
static constexpr int AT_SQ = 0;
static constexpr int AT_ST = 64 * APAD;            // 2 buffers
static constexpr int AT_SS = AT_ST + 2 * 64 * APAD;
static constexpr int ATT_SMEM = (AT_SS + 64 * SPAD) * 4;  // 184320 B

__global__ __launch_bounds__(256) void attn_mma(
    const float* __restrict__ q, const float* __restrict__ kin,
    const float* __restrict__ v, const int* __restrict__ adj,
    float* __restrict__ out)
{
    extern __shared__ float dsm[];
    float (*sQ)[APAD] = (float (*)[APAD])(dsm + AT_SQ);
    float* ssm        = dsm + AT_SS;

    const int tid  = threadIdx.x;
    const int wid  = tid >> 5, lane = tid & 31;
    const int grp  = lane >> 2, tid4 = lane & 3;
    const int m0   = (wid >> 1) * 16;
    const int n0   = (wid & 1) * 32;
    const int bh   = blockIdx.y;
    const int bb   = bh / HEADS, hh = bh % HEADS;
    const int q0   = blockIdx.x * 64;

    const float* qb = q   + (size_t)bh * SEQ * HDIM + (size_t)q0 * HDIM;
    const float* kb = kin + (size_t)bh * SEQ * HDIM;
    const float* vb = v   + (size_t)bh * SEQ * HDIM;

    // stage a 64x64 tile into a [64][APAD] buffer (4 x 16B per thread)
    auto stage64 = [&](float (*dst)[APAD], const float* src) {
        #pragma unroll
        for (int it = 0; it < 4; it++) {
            int c = tid + it * 256;
            int r = c >> 4, col = (c & 15) << 2;
            CP_ASYNC16(smem_u32(&dst[r][col]), src + r * HDIM + col);
        }
    };
    float (*sT0)[APAD] = (float (*)[APAD])(dsm + AT_ST);
    float (*sT1)[APAD] = (float (*)[APAD])(dsm + AT_ST + 64 * APAD);

    // Prologue: Q + K0
    stage64(sQ, qb);
    stage64(sT0, kb);
    CP_COMMIT();

    const float scale = 0.125f;

    // ---- Phase 1: scores ----
    for (int kt = 0; kt < 8; kt++) {
        CP_WAIT(0);
        __syncthreads();
        if (kt + 1 < 8) stage64((kt + 1) & 1 ? sT1 : sT0, kb + (size_t)(kt + 1) * 64 * HDIM);
        CP_COMMIT();

        float (*sK)[APAD] = (kt & 1) ? sT1 : sT0;
        float accs[4][4];
        #pragma unroll
        for (int j = 0; j < 4; j++)
            #pragma unroll
            for (int r = 0; r < 4; r++) accs[j][r] = 0.f;

        #pragma unroll
        for (int ks = 0; ks < 8; ks++) {
            const int k0 = ks * 8;
            uint32_t af[4];
            af[0] = __float_as_uint(sQ[m0 + grp    ][k0 + tid4    ]);
            af[1] = __float_as_uint(sQ[m0 + grp + 8][k0 + tid4    ]);
            af[2] = __float_as_uint(sQ[m0 + grp    ][k0 + tid4 + 4]);
            af[3] = __float_as_uint(sQ[m0 + grp + 8][k0 + tid4 + 4]);
            #pragma unroll
            for (int j = 0; j < 4; j++) {
                uint32_t bf[2];
                bf[0] = __float_as_uint(sK[n0 + j * 8 + grp][k0 + tid4    ]);
                bf[1] = __float_as_uint(sK[n0 + j * 8 + grp][k0 + tid4 + 4]);
                mma_tf32(accs[j], af, bf);
            }
        }

        // mask + store scores
        const int rlo = m0 + grp, rhi = rlo + 8;
        const int arow_lo = ((size_t)0, ((bb * SEQ) + q0 + rlo)) * SEQ;
        const int arow_hi = ((bb * SEQ) + q0 + rhi) * SEQ;
        #pragma unroll
        for (int j = 0; j < 4; j++) {
            int col = kt * 64 + n0 + j * 8 + tid4 * 2;
            int2 a0 = *(const int2*)(adj + (size_t)arow_lo + col);
            int2 a1 = *(const int2*)(adj + (size_t)arow_hi + col);
            float s00 = accs[j][0] * scale, s01 = accs[j][1] * scale;
            float s10 = accs[j][2] * scale, s11 = accs[j][3] * scale;
            if (a0.x == 0) s00 = -1e30f;
            if (a0.y == 0) s01 = -1e30f;
            if (a1.x == 0) s10 = -1e30f;
            if (a1.y == 0) s11 = -1e30f;
            *(float2*)(ssm + rlo * SPAD + col) = make_float2(s00, s01);
            *(float2*)(ssm + rhi * SPAD + col) = make_float2(s10, s11);
        }
        __syncthreads();
    }

    // Issue V0 early (overlaps softmax)
    stage64(sT0, vb);
    CP_COMMIT();

    // ---- Phase 2: softmax (warp per row), write rounded probs ----
    for (int rr = 0; rr < 8; rr++) {
        int qi = wid * 8 + rr;
        float* row = ssm + qi * SPAD;
        float mx = -1e30f;
        #pragma unroll
        for (int i = 0; i < 16; i++) mx = fmaxf(mx, row[lane + i * 32]);
        #pragma unroll
        for (int o = 16; o > 0; o >>= 1) mx = fmaxf(mx, __shfl_xor_sync(0xffffffffu, mx, o));
        float e[16], sum = 0.f;
        #pragma unroll
        for (int i = 0; i < 16; i++) { e[i] = __expf(row[lane + i * 32] - mx); sum += e[i]; }
        #pragma unroll
        for (int o = 16; o > 0; o >>= 1) sum += __shfl_xor_sync(0xffffffffu, sum, o);
        float inv = 1.0f / sum;
        #pragma unroll
        for (int i = 0; i < 16; i++) row[lane + i * 32] = f2tf32f(e[i] * inv);
    }

    // ---- Phase 3: out = P @ V ----
    float acco[4][4];
    #pragma unroll
    for (int j = 0; j < 4; j++)
        #pragma unroll
        for (int r = 0; r < 4; r++) acco[j][r] = 0.f;

    for (int kt = 0; kt < 8; kt++) {
        CP_WAIT(0);
        __syncthreads();
        if (kt + 1 < 8) stage64((kt + 1) & 1 ? sT1 : sT0, vb + (size_t)(kt + 1) * 64 * HDIM);
        CP_COMMIT();

        float (*sV)[APAD] = (kt & 1) ? sT1 : sT0;
        #pragma unroll
        for (int ks = 0; ks < 8; ks++) {
            const int kk0 = ks * 8;
            const int kcol = kt * 64 + kk0;
            uint32_t af[4];
            af[0] = __float_as_uint(ssm[(m0 + grp    ) * SPAD + kcol + tid4    ]);
            af[1] = __float_as_uint(ssm[(m0 + grp + 8) * SPAD + kcol + tid4    ]);
            af[2] = __float_as_uint(ssm[(m0 + grp    ) * SPAD + kcol + tid4 + 4]);
            af[3] = __float_as_uint(ssm[(m0 + grp + 8) * SPAD + kcol + tid4 + 4]);
            #pragma unroll
            for (int j = 0; j < 4; j++) {
                uint32_t bf[2];
                bf[0] = __float_as_uint(sV[kk0 + tid4    ][n0 + j * 8 + grp]);
                bf[1] = __float_as_uint(sV[kk0 + tid4 + 4][n0 + j * 8 + grp]);
                mma_tf32(acco[j], af, bf);
            }
        }
        __syncthreads();
    }

    // Store rounded output to [B, N, 768]
    const int rlo = q0 + m0 + grp, rhi = rlo + 8;
    #pragma unroll
    for (int j = 0; j < 4; j++) {
        int d = hh * HDIM + n0 + j * 8 + tid4 * 2;
        *(float2*)(out + ((size_t)bb * SEQ + rlo) * DIM + d) =
            make_float2(f2tf32f(acco[j][0]), f2tf32f(acco[j][1]));
        *(float2*)(out + ((size_t)bb * SEQ + rhi) * DIM + d) =
            make_float2(f2tf32f(acco[j][2]), f2tf32f(acco[j][3]));
    }
}

// ---------------------------------------------------------------------------
extern "C" void kernel_launch(void* const* d_in, const int* in_sizes, int n_in,
                              void* d_out, int out_size)
{
    const float* x   = (const float*)d_in[0];
    const int*   adj = (const int*)  d_in[1];
    const float* wq  = (const float*)d_in[2];
    const float* bq  = (const float*)d_in[3];
    const float* wk  = (const float*)d_in[4];
    const float* bk  = (const float*)d_in[5];
    const float* wv  = (const float*)d_in[6];
    const float* bv  = (const float*)d_in[7];
    const float* wo  = (const float*)d_in[8];
    const float* bo  = (const float*)d_in[9];
    const float* g1  = (const float*)d_in[10];
    const float* b1  = (const float*)d_in[11];
    const float* g2  = (const float*)d_in[12];
    const float* b2  = (const float*)d_in[13];
    const float* w1  = (const float*)d_in[14];
    const float* bf1 = (const float*)d_in[15];
    const float* w2  = (const float*)d_in[16];
    const float* bf2 = (const float*)d_in[17];
    float* out = (float*)d_out;

    float *ph, *pq, *pk, *pv, *pout1, *pffn, *pwt;
    cudaGetSymbolAddress((void**)&ph,    g_h);
    cudaGetSymbolAddress((void**)&pq,    g_q);
    cudaGetSymbolAddress((void**)&pk,    g_k);
    cudaGetSymbolAddress((void**)&pv,    g_v);
    cudaGetSymbolAddress((void**)&pout1, g_out1);
    cudaGetSymbolAddress((void**)&pffn,  g_ffn);
    cudaGetSymbolAddress((void**)&pwt,   g_wt);

    float* wqR = pwt;
    float* wkR = pwt + DIM * DIM;
    float* wvR = pwt + 2 * DIM * DIM;
    float* woR = pwt + 3 * DIM * DIM;
    float* w1R = pwt + 4 * DIM * DIM;
    float* w2R = pwt + 4 * DIM * DIM + DIM * DFF;

    static bool attr_set = false;
    if (!attr_set) {
        cudaFuncSetAttribute(attn_mma,  cudaFuncAttributeMaxDynamicSharedMemorySize, ATT_SMEM);
        cudaFuncSetAttribute(mma_gemm<0>, cudaFuncAttributeMaxDynamicSharedMemorySize, GEMM_SMEM);
        cudaFuncSetAttribute(mma_gemm<1>, cudaFuncAttributeMaxDynamicSharedMemorySize, GEMM_SMEM);
        cudaFuncSetAttribute(mma_gemm<2>, cudaFuncAttributeMaxDynamicSharedMemorySize, GEMM_SMEM);
        attr_set = true;
    }

    // 0. Round weights to tf32 (once per launch; graph-capturable)
    const int wsz = DIM * DIM;          // 589824
    const int fsz = DIM * DFF;          // 2359296
    round_kernel<<<wsz / 1024, 256>>>(wq, wqR, wsz);
    round_kernel<<<wsz / 1024, 256>>>(wk, wkR, wsz);
    round_kernel<<<wsz / 1024, 256>>>(wv, wvR, wsz);
    round_kernel<<<wsz / 1024, 256>>>(wo, woR, wsz);
    round_kernel<<<fsz / 1024, 256>>>(w1, w1R, fsz);
    round_kernel<<<fsz / 1024, 256>>>(w2, w2R, fsz);

    // 1. LN1 (rounded out)
    ln_kernel<<<MROWS, 256>>>(x, g1, b1, ph);

    // 2-4. QKV projections
    dim3 g768(DIM / 128, MROWS / 128);
    mma_gemm<0><<<g768, 256, GEMM_SMEM>>>(ph, wqR, bq, nullptr, pq, DIM, DIM);
    mma_gemm<0><<<g768, 256, GEMM_SMEM>>>(ph, wkR, bk, nullptr, pk, DIM, DIM);
    mma_gemm<0><<<g768, 256, GEMM_SMEM>>>(ph, wvR, bv, nullptr, pv, DIM, DIM);

    // 5. Attention (tensor-core), writes rounded [B,N,DIM] into g_h
    attn_mma<<<dim3(SEQ / 64, BATCH * HEADS), 256, ATT_SMEM>>>(pq, pk, pv, adj, ph);

    // 6. Output projection + bias + residual(x) (fp32 out)
    mma_gemm<1><<<g768, 256, GEMM_SMEM>>>(ph, woR, bo, x, pout1, DIM, DIM);

    // 7. LN2 (rounded out)
    ln_kernel<<<MROWS, 256>>>(pout1, g2, b2, pq);

    // 8. FFN1 + GELU (rounded out)
    dim3 g3072(DFF / 128, MROWS / 128);
    mma_gemm<2><<<g3072, 256, GEMM_SMEM>>>(pq, w1R, bf1, nullptr, pffn, DFF, DIM);

    // 9. FFN2 + bias + residual(out1) -> final output (fp32)
    mma_gemm<1><<<g768, 256, GEMM_SMEM>>>(pffn, w2R, bf2, pout1, out, DIM, DFF);
}

// round 7
// speedup vs baseline: 3.3816x; 1.1456x over previous
#include <cuda_runtime.h>
#include <math.h>
#include <stdint.h>

// Problem constants
static constexpr int BATCH = 32;
static constexpr int SEQ   = 512;
static constexpr int DIM   = 768;
static constexpr int HEADS = 12;
static constexpr int HDIM  = 64;
static constexpr int MROWS = BATCH * SEQ;   // 16384
static constexpr int DFF   = 3072;

// Scratch (device globals — allocation-free rule)
__device__ float g_h   [MROWS * DIM];
__device__ float g_q   [MROWS * DIM];
__device__ float g_k   [MROWS * DIM];
__device__ float g_v   [MROWS * DIM];
__device__ float g_out1[MROWS * DIM];
__device__ float g_ffn [MROWS * DFF];
// tf32-rounded weights: wq,wk,wv,wo (768x768), w1 (768x3072), w2 (3072x768)
__device__ float g_wt  [4 * DIM * DIM + 2 * DIM * DFF];

// ---------------------------------------------------------------------------
// Helpers
// ---------------------------------------------------------------------------
__device__ __forceinline__ uint32_t smem_u32(const void* p) {
    uint32_t a;
    asm("{ .reg .u64 t; cvta.to.shared.u64 t, %1; cvt.u32.u64 %0, t; }" : "=r"(a) : "l"(p));
    return a;
}
__device__ __forceinline__ float f2tf32f(float x) {
    uint32_t r; asm("cvt.rna.tf32.f32 %0, %1;" : "=r"(r) : "f"(x));
    return __uint_as_float(r);
}
__device__ __forceinline__ void mma_tf32(float* c, const uint32_t* a, const uint32_t* b) {
    asm volatile(
        "mma.sync.aligned.m16n8k8.row.col.f32.tf32.tf32.f32 "
        "{%0,%1,%2,%3}, {%4,%5,%6,%7}, {%8,%9}, {%0,%1,%2,%3};"
        : "+f"(c[0]), "+f"(c[1]), "+f"(c[2]), "+f"(c[3])
        : "r"(a[0]), "r"(a[1]), "r"(a[2]), "r"(a[3]), "r"(b[0]), "r"(b[1]));
}
#define CP_ASYNC16(dst, src) \
    asm volatile("cp.async.cg.shared.global [%0], [%1], 16;" :: "r"(dst), "l"(src))
#define CP_COMMIT()  asm volatile("cp.async.commit_group;" ::: "memory")
#define CP_WAIT(N)   asm volatile("cp.async.wait_group %0;" :: "n"(N) : "memory")

// ---------------------------------------------------------------------------
// Round ALL weights to tf32 in one launch (also keeps launch idx 5 = attn)
// g_wt layout: wq, wk, wv, wo, w1, w2
// ---------------------------------------------------------------------------
__global__ __launch_bounds__(256) void round_all(
    const float* __restrict__ wq, const float* __restrict__ wk,
    const float* __restrict__ wv, const float* __restrict__ wo,
    const float* __restrict__ w1, const float* __restrict__ w2,
    float* __restrict__ dst)
{
    const int W4 = DIM * DIM / 4;      // 147456
    const int F4 = DIM * DFF / 4;      // 589824
    int i4 = blockIdx.x * 256 + threadIdx.x;
    const float* src; int off;
    if (i4 < 4 * W4) {
        int r = i4 / W4; off = i4 - r * W4;
        src = (r == 0) ? wq : (r == 1) ? wk : (r == 2) ? wv : wo;
    } else if (i4 < 4 * W4 + F4) {
        src = w1; off = i4 - 4 * W4;
    } else {
        src = w2; off = i4 - 4 * W4 - F4;
    }
    float4 v = ((const float4*)src)[off];
    ((float4*)dst)[i4] = make_float4(f2tf32f(v.x), f2tf32f(v.y),
                                     f2tf32f(v.z), f2tf32f(v.w));
}

// ---------------------------------------------------------------------------
// tf32 mma.sync GEMM, cp.async 4-stage pipeline, ONE sync per stage.
// C[M,Nc] = A[M,K] @ W[K,Nc] (+epilogue). A and W pre-rounded to tf32.
// CTA 128x128, 8 warps (4x2), warp tile 32x64, K-stage 16.
// EPI 0: +bias, permuted+rounded store to [B,H,N,HD] (feeds attention)
// EPI 1: +bias +res (fp32 exact)
// EPI 2: +bias, exact GELU, rounded (feeds next GEMM)
// ---------------------------------------------------------------------------
static constexpr int GSTAGES = 4;
static constexpr int GEMM_SMEM = GSTAGES * (128 * 20 + 16 * 136) * 4;  // 75776 B

template <int EPI>
__global__ __launch_bounds__(256, 2) void mma_gemm(
    const float* __restrict__ A, const float* __restrict__ W,
    const float* __restrict__ bias, const float* __restrict__ res,
    float* __restrict__ C, int Nc, int K)
{
    extern __shared__ float dsm[];
    float (*smA)[128][20] = (float (*)[128][20])dsm;
    float (*smB)[16][136] = (float (*)[16][136])(dsm + GSTAGES * 128 * 20);

    const int tid  = threadIdx.x;
    const int wid  = tid >> 5, lane = tid & 31;
    const int grp  = lane >> 2, tid4 = lane & 3;
    const int wm   = (wid >> 1) * 32;
    const int wn   = (wid & 1) * 64;
    const int row0 = blockIdx.y * 128;
    const int col0 = blockIdx.x * 128;

    const int am  = tid >> 2;
    const int akq = (tid & 3) << 2;
    const int bk  = tid >> 5;
    const int bn4 = (tid & 31) << 2;

    float acc[2][8][4];
    #pragma unroll
    for (int t = 0; t < 2; t++)
        #pragma unroll
        for (int j = 0; j < 8; j++)
            #pragma unroll
            for (int r = 0; r < 4; r++) acc[t][j][r] = 0.f;

    const int nst = K >> 4;

    auto issue = [&](int s) {
        const int b = s & 3;
        const int k0 = s << 4;
        #pragma unroll
        for (int it = 0; it < 2; it++) {
            int m = am + it * 64;
            CP_ASYNC16(smem_u32(&smA[b][m][akq]),
                       A + (size_t)(row0 + m) * K + k0 + akq);
            int k = bk + it * 8;
            CP_ASYNC16(smem_u32(&smB[b][k][bn4]),
                       W + (size_t)(k0 + k) * Nc + col0 + bn4);
        }
    };

    issue(0); CP_COMMIT();
    issue(1); CP_COMMIT();
    issue(2); CP_COMMIT();

    for (int st = 0; st < nst; st++) {
        CP_WAIT(2);
        __syncthreads();

        const int bf = st & 3;
        #pragma unroll
        for (int s = 0; s < 2; s++) {
            uint32_t af[2][4];
            #pragma unroll
            for (int t = 0; t < 2; t++) {
                int r = wm + t * 16 + grp;
                af[t][0] = __float_as_uint(smA[bf][r    ][s * 8 + tid4    ]);
                af[t][1] = __float_as_uint(smA[bf][r + 8][s * 8 + tid4    ]);
                af[t][2] = __float_as_uint(smA[bf][r    ][s * 8 + tid4 + 4]);
                af[t][3] = __float_as_uint(smA[bf][r + 8][s * 8 + tid4 + 4]);
            }
            uint32_t bfr[8][2];
            #pragma unroll
            for (int j = 0; j < 8; j++) {
                int c = wn + j * 8 + grp;
                bfr[j][0] = __float_as_uint(smB[bf][s * 8 + tid4    ][c]);
                bfr[j][1] = __float_as_uint(smB[bf][s * 8 + tid4 + 4][c]);
            }
            #pragma unroll
            for (int t = 0; t < 2; t++)
                #pragma unroll
                for (int j = 0; j < 8; j++)
                    mma_tf32(acc[t][j], af[t], bfr[j]);
        }
        // Issue next stage AFTER compute: the top-of-loop barrier already
        // guarantees every warp finished reading the buffer being overwritten.
        if (st + 3 < nst) issue(st + 3);
        CP_COMMIT();
    }

    // Epilogue
    #pragma unroll
    for (int t = 0; t < 2; t++) {
        int r_lo = row0 + wm + t * 16 + grp;
        int r_hi = r_lo + 8;
        #pragma unroll
        for (int j = 0; j < 8; j++) {
            int c = col0 + wn + j * 8 + tid4 * 2;
            float b0 = bias[c], b1 = bias[c + 1];
            float v00 = acc[t][j][0] + b0, v01 = acc[t][j][1] + b1;
            float v10 = acc[t][j][2] + b0, v11 = acc[t][j][3] + b1;
            if (EPI == 0) {
                v00 = f2tf32f(v00); v01 = f2tf32f(v01);
                v10 = f2tf32f(v10); v11 = f2tf32f(v11);
                int h = c >> 6, d = c & 63;
                int blo = r_lo >> 9, nlo = r_lo & 511;
                int bhi = r_hi >> 9, nhi = r_hi & 511;
                *(float2*)(C + (((size_t)(blo * HEADS + h)) * SEQ + nlo) * HDIM + d) =
                    make_float2(v00, v01);
                *(float2*)(C + (((size_t)(bhi * HEADS + h)) * SEQ + nhi) * HDIM + d) =
                    make_float2(v10, v11);
            } else if (EPI == 1) {
                const float2 r0 = *(const float2*)(res + (size_t)r_lo * Nc + c);
                const float2 r1 = *(const float2*)(res + (size_t)r_hi * Nc + c);
                *(float2*)(C + (size_t)r_lo * Nc + c) = make_float2(v00 + r0.x, v01 + r0.y);
                *(float2*)(C + (size_t)r_hi * Nc + c) = make_float2(v10 + r1.x, v11 + r1.y);
            } else {
                const float is2 = 0.70710678118654752f;
                v00 = f2tf32f(0.5f * v00 * (1.0f + erff(v00 * is2)));
                v01 = f2tf32f(0.5f * v01 * (1.0f + erff(v01 * is2)));
                v10 = f2tf32f(0.5f * v10 * (1.0f + erff(v10 * is2)));
                v11 = f2tf32f(0.5f * v11 * (1.0f + erff(v11 * is2)));
                *(float2*)(C + (size_t)r_lo * Nc + c) = make_float2(v00, v01);
                *(float2*)(C + (size_t)r_hi * Nc + c) = make_float2(v10, v11);
            }
        }
    }
}

// ---------------------------------------------------------------------------
// LayerNorm: one block per row of 768; writes tf32-rounded (feeds GEMM A)
// ---------------------------------------------------------------------------
__global__ __launch_bounds__(256) void ln_kernel(
    const float* __restrict__ x, const float* __restrict__ g,
    const float* __restrict__ b, float* __restrict__ y)
{
    int row = blockIdx.x;
    int tid = threadIdx.x;
    const float* xr = x + (size_t)row * DIM;
    float v0 = xr[tid], v1 = xr[tid + 256], v2 = xr[tid + 512];
    float s  = v0 + v1 + v2;
    float ss = v0 * v0 + v1 * v1 + v2 * v2;
    #pragma unroll
    for (int o = 16; o > 0; o >>= 1) {
        s  += __shfl_xor_sync(0xffffffffu, s, o);
        ss += __shfl_xor_sync(0xffffffffu, ss, o);
    }
    __shared__ float sh_s[8], sh_ss[8];
    int w = tid >> 5, l = tid & 31;
    if (l == 0) { sh_s[w] = s; sh_ss[w] = ss; }
    __syncthreads();
    float ts = 0.f, tss = 0.f;
    #pragma unroll
    for (int i = 0; i < 8; i++) { ts += sh_s[i]; tss += sh_ss[i]; }
    float mean = ts * (1.0f / DIM);
    float var  = tss * (1.0f / DIM) - mean * mean;
    float inv  = rsqrtf(var + 1e-5f);
    float* yr = y + (size_t)row * DIM;
    yr[tid]       = f2tf32f((v0 - mean) * inv * g[tid]       + b[tid]);
    yr[tid + 256] = f2tf32f((v1 - mean) * inv * g[tid + 256] + b[tid + 256]);
    yr[tid + 512] = f2tf32f((v2 - mean) * inv * g[tid + 512] + b[tid + 512]);
}

// ---------------------------------------------------------------------------
// Flash-style masked attention on mma.sync tf32 (online softmax).
// Grid (SEQ/64, B*H), 256 threads (8 warps, 4 row-groups x 2 halves).
// Warp tile: rows m0..m0+15, score/output cols n0..n0+31.
// Smem: Q[64][68], K 2x[64][68], V 2x[64][72], P[64][68], red[64][2] float2.
// ---------------------------------------------------------------------------
static constexpr int KP = 68;
static constexpr int VP = 72;
static constexpr int F_SQ  = 0;
static constexpr int F_SK  = F_SQ + 64 * KP;
static constexpr int F_SV  = F_SK + 2 * 64 * KP;
static constexpr int F_SP  = F_SV + 2 * 64 * VP;
static constexpr int F_RED = F_SP + 64 * KP;
static constexpr int ATT_SMEM = (F_RED + 64 * 4) * 4;   // 107520 B

__global__ __launch_bounds__(256) void attn_flash(
    const float* __restrict__ q, const float* __restrict__ kin,
    const float* __restrict__ v, const int* __restrict__ adj,
    float* __restrict__ out)
{
    extern __shared__ float dsm[];
    float* sQb = dsm + F_SQ;
    float* sKb = dsm + F_SK;
    float* sVb = dsm + F_SV;
    float* sP  = dsm + F_SP;
    float2* sRed = (float2*)(dsm + F_RED);   // [row][half]

    const int tid  = threadIdx.x;
    const int wid  = tid >> 5, lane = tid & 31;
    const int grp  = lane >> 2, tid4 = lane & 3;
    const int m0   = (wid >> 1) * 16;
    const int half = wid & 1;
    const int n0   = half * 32;
    const int bh   = blockIdx.y;
    const int bb   = bh / HEADS, hh = bh % HEADS;
    const int q0   = blockIdx.x * 64;

    const float* qb = q   + (size_t)bh * SEQ * HDIM + (size_t)q0 * HDIM;
    const float* kb = kin + (size_t)bh * SEQ * HDIM;
    const float* vb = v   + (size_t)bh * SEQ * HDIM;

    auto stage = [&](float* dst, int pitch, const float* src) {
        #pragma unroll
        for (int it = 0; it < 4; it++) {
            int c = tid + it * 256;
            int r = c >> 4, col = (c & 15) << 2;
            CP_ASYNC16(smem_u32(dst + r * pitch + col), src + r * HDIM + col);
        }
    };

    // Prologue: Q + K0 + V0
    stage(sQb, KP, qb);
    stage(sKb, KP, kb);
    stage(sVb, VP, vb);
    CP_COMMIT();

    float m_run[2] = {-1e30f, -1e30f};
    float l_run[2] = {0.f, 0.f};
    float acc[4][4];
    #pragma unroll
    for (int j = 0; j < 4; j++)
        #pragma unroll
        for (int r = 0; r < 4; r++) acc[j][r] = 0.f;

    const float scale = 0.125f;

    for (int kt = 0; kt < 8; kt++) {
        CP_WAIT(0);
        __syncthreads();
        if (kt + 1 < 8) {
            stage(sKb + ((kt + 1) & 1) * 64 * KP, KP, kb + (size_t)(kt + 1) * 64 * HDIM);
            stage(sVb + ((kt + 1) & 1) * 64 * VP, VP, vb + (size_t)(kt + 1) * 64 * HDIM);
        }
        CP_COMMIT();

        const float* sK = sKb + (kt & 1) * 64 * KP;
        const float* sV = sVb + (kt & 1) * 64 * VP;

        // ---- scores: m16 x n32 (this warp's key half) ----
        float sacc[4][4];
        #pragma unroll
        for (int j = 0; j < 4; j++)
            #pragma unroll
            for (int r = 0; r < 4; r++) sacc[j][r] = 0.f;

        #pragma unroll
        for (int ks = 0; ks < 8; ks++) {
            const int k0 = ks * 8;
            uint32_t af[4];
            af[0] = __float_as_uint(sQb[(m0 + grp    ) * KP + k0 + tid4    ]);
            af[1] = __float_as_uint(sQb[(m0 + grp + 8) * KP + k0 + tid4    ]);
            af[2] = __float_as_uint(sQb[(m0 + grp    ) * KP + k0 + tid4 + 4]);
            af[3] = __float_as_uint(sQb[(m0 + grp + 8) * KP + k0 + tid4 + 4]);
            #pragma unroll
            for (int j = 0; j < 4; j++) {
                uint32_t bf[2];
                bf[0] = __float_as_uint(sK[(n0 + j * 8 + grp) * KP + k0 + tid4    ]);
                bf[1] = __float_as_uint(sK[(n0 + j * 8 + grp) * KP + k0 + tid4 + 4]);
                mma_tf32(sacc[j], af, bf);
            }
        }

        // ---- scale + adjacency mask ----
        const int rlo_g = q0 + m0 + grp, rhi_g = rlo_g + 8;
        const size_t arow_lo = ((size_t)bb * SEQ + rlo_g) * SEQ;
        const size_t arow_hi = ((size_t)bb * SEQ + rhi_g) * SEQ;
        #pragma unroll
        for (int j = 0; j < 4; j++) {
            int col = kt * 64 + n0 + j * 8 + tid4 * 2;
            int2 a0 = *(const int2*)(adj + arow_lo + col);
            int2 a1 = *(const int2*)(adj + arow_hi + col);
            sacc[j][0] = (a0.x == 0) ? -1e30f : sacc[j][0] * scale;
            sacc[j][1] = (a0.y == 0) ? -1e30f : sacc[j][1] * scale;
            sacc[j][2] = (a1.x == 0) ? -1e30f : sacc[j][2] * scale;
            sacc[j][3] = (a1.y == 0) ? -1e30f : sacc[j][3] * scale;
        }

        // ---- half-stats: row max over this warp's 32 cols ----
        float hm0 = -1e30f, hm1 = -1e30f;
        #pragma unroll
        for (int j = 0; j < 4; j++) {
            hm0 = fmaxf(hm0, fmaxf(sacc[j][0], sacc[j][1]));
            hm1 = fmaxf(hm1, fmaxf(sacc[j][2], sacc[j][3]));
        }
        hm0 = fmaxf(hm0, __shfl_xor_sync(0xffffffffu, hm0, 1));
        hm0 = fmaxf(hm0, __shfl_xor_sync(0xffffffffu, hm0, 2));
        hm1 = fmaxf(hm1, __shfl_xor_sync(0xffffffffu, hm1, 1));
        hm1 = fmaxf(hm1, __shfl_xor_sync(0xffffffffu, hm1, 2));

        // e-values (relative to half max) with masked->0, and half sums
        float hs0 = 0.f, hs1 = 0.f;
        #pragma unroll
        for (int j = 0; j < 4; j++) {
            float e0 = (sacc[j][0] > -1e29f) ? __expf(sacc[j][0] - hm0) : 0.f;
            float e1 = (sacc[j][1] > -1e29f) ? __expf(sacc[j][1] - hm0) : 0.f;
            float e2 = (sacc[j][2] > -1e29f) ? __expf(sacc[j][2] - hm1) : 0.f;
            float e3 = (sacc[j][3] > -1e29f) ? __expf(sacc[j][3] - hm1) : 0.f;
            sacc[j][0] = e0; sacc[j][1] = e1; sacc[j][2] = e2; sacc[j][3] = e3;
            hs0 += e0 + e1; hs1 += e2 + e3;
        }
        hs0 += __shfl_xor_sync(0xffffffffu, hs0, 1);
        hs0 += __shfl_xor_sync(0xffffffffu, hs0, 2);
        hs1 += __shfl_xor_sync(0xffffffffu, hs1, 1);
        hs1 += __shfl_xor_sync(0xffffffffu, hs1, 2);

        if (tid4 == 0) {
            sRed[(m0 + grp    ) * 2 + half] = make_float2(hm0, hs0);
            sRed[(m0 + grp + 8) * 2 + half] = make_float2(hm1, hs1);
        }
        __syncthreads();

        // ---- merge halves, update running stats, rescale acc ----
        float psc[2], fct[2];
        #pragma unroll
        for (int r = 0; r < 2; r++) {
            int row = m0 + grp + r * 8;
            float2 A = sRed[row * 2 + 0];
            float2 B = sRed[row * 2 + 1];
            float mt = fmaxf(A.x, B.x);
            float mn = fmaxf(m_run[r], mt);
            float f  = __expf(m_run[r] - mn);           // 0 if first tile w/ real keys
            float sA = A.y * __expf(A.x - mn);          // A.y==0 kills bogus exp(0)
            float sB = B.y * __expf(B.x - mn);
            l_run[r] = l_run[r] * f + sA + sB;
            float hmr = (r == 0) ? ((half == 0) ? A.x : B.x) : ((half == 0) ? A.x : B.x);
            // note: own-half max equals hm0/hm1; recompute from sRed for uniformity
            psc[r] = __expf(((half == 0) ? A.x : B.x) - mn);
            fct[r] = f;
            m_run[r] = mn;
            (void)hmr;
        }
        #pragma unroll
        for (int j = 0; j < 4; j++) {
            acc[j][0] *= fct[0]; acc[j][1] *= fct[0];
            acc[j][2] *= fct[1]; acc[j][3] *= fct[1];
        }

        // ---- write P tile (tf32-rounded) ----
        #pragma unroll
        for (int j = 0; j < 4; j++) {
            int col = n0 + j * 8 + tid4 * 2;
            *(float2*)(sP + (m0 + grp    ) * KP + col) =
                make_float2(f2tf32f(sacc[j][0] * psc[0]), f2tf32f(sacc[j][1] * psc[0]));
            *(float2*)(sP + (m0 + grp + 8) * KP + col) =
                make_float2(f2tf32f(sacc[j][2] * psc[1]), f2tf32f(sacc[j][3] * psc[1]));
        }
        __syncthreads();

        // ---- P @ V accumulate ----
        #pragma unroll
        for (int kc = 0; kc < 8; kc++) {
            const int kk0 = kc * 8;
            uint32_t af[4];
            af[0] = __float_as_uint(sP[(m0 + grp    ) * KP + kk0 + tid4    ]);
            af[1] = __float_as_uint(sP[(m0 + grp + 8) * KP + kk0 + tid4    ]);
            af[2] = __float_as_uint(sP[(m0 + grp    ) * KP + kk0 + tid4 + 4]);
            af[3] = __float_as_uint(sP[(m0 + grp + 8) * KP + kk0 + tid4 + 4]);
            #pragma unroll
            for (int j = 0; j < 4; j++) {
                uint32_t bf[2];
                bf[0] = __float_as_uint(sV[(kk0 + tid4    ) * VP + n0 + j * 8 + grp]);
                bf[1] = __float_as_uint(sV[(kk0 + tid4 + 4) * VP + n0 + j * 8 + grp]);
                mma_tf32(acc[j], af, bf);
            }
        }
    }

    // ---- finalize: divide by l, store rounded to [B, N, 768] ----
    const float inv0 = 1.0f / l_run[0];
    const float inv1 = 1.0f / l_run[1];
    const int rlo = q0 + m0 + grp, rhi = rlo + 8;
    #pragma unroll
    for (int j = 0; j < 4; j++) {
        int d = hh * HDIM + n0 + j * 8 + tid4 * 2;
        *(float2*)(out + ((size_t)bb * SEQ + rlo) * DIM + d) =
            make_float2(f2tf32f(acc[j][0] * inv0), f2tf32f(acc[j][1] * inv0));
        *(float2*)(out + ((size_t)bb * SEQ + rhi) * DIM + d) =
            make_float2(f2tf32f(acc[j][2] * inv1), f2tf32f(acc[j][3] * inv1));
    }
}

// ---------------------------------------------------------------------------
extern "C" void kernel_launch(void* const* d_in, const int* in_sizes, int n_in,
                              void* d_out, int out_size)
{
    const float* x   = (const float*)d_in[0];
    const int*   adj = (const int*)  d_in[1];
    const float* wq  = (const float*)d_in[2];
    const float* bq  = (const float*)d_in[3];
    const float* wk  = (const float*)d_in[4];
    const float* bk  = (const float*)d_in[5];
    const float* wv  = (const float*)d_in[6];
    const float* bv  = (const float*)d_in[7];
    const float* wo  = (const float*)d_in[8];
    const float* bo  = (const float*)d_in[9];
    const float* g1  = (const float*)d_in[10];
    const float* b1  = (const float*)d_in[11];
    const float* g2  = (const float*)d_in[12];
    const float* b2  = (const float*)d_in[13];
    const float* w1  = (const float*)d_in[14];
    const float* bf1 = (const float*)d_in[15];
    const float* w2  = (const float*)d_in[16];
    const float* bf2 = (const float*)d_in[17];
    float* out = (float*)d_out;

    float *ph, *pq, *pk, *pv, *pout1, *pffn, *pwt;
    cudaGetSymbolAddress((void**)&ph,    g_h);
    cudaGetSymbolAddress((void**)&pq,    g_q);
    cudaGetSymbolAddress((void**)&pk,    g_k);
    cudaGetSymbolAddress((void**)&pv,    g_v);
    cudaGetSymbolAddress((void**)&pout1, g_out1);
    cudaGetSymbolAddress((void**)&pffn,  g_ffn);
    cudaGetSymbolAddress((void**)&pwt,   g_wt);

    float* wqR = pwt;
    float* wkR = pwt + DIM * DIM;
    float* wvR = pwt + 2 * DIM * DIM;
    float* woR = pwt + 3 * DIM * DIM;
    float* w1R = pwt + 4 * DIM * DIM;
    float* w2R = pwt + 4 * DIM * DIM + DIM * DFF;

    static bool attr_set = false;
    if (!attr_set) {
        cudaFuncSetAttribute(attn_flash, cudaFuncAttributeMaxDynamicSharedMemorySize, ATT_SMEM);
        cudaFuncSetAttribute(mma_gemm<0>, cudaFuncAttributeMaxDynamicSharedMemorySize, GEMM_SMEM);
        cudaFuncSetAttribute(mma_gemm<1>, cudaFuncAttributeMaxDynamicSharedMemorySize, GEMM_SMEM);
        cudaFuncSetAttribute(mma_gemm<2>, cudaFuncAttributeMaxDynamicSharedMemorySize, GEMM_SMEM);
        attr_set = true;
    }

    // 0. Round all weights to tf32 (single launch)
    const int total4 = (4 * DIM * DIM + 2 * DIM * DFF) / 4;   // 1769472
    round_all<<<total4 / 256, 256>>>(wq, wk, wv, wo, w1, w2, pwt);

    // 1. LN1 (rounded out)
    ln_kernel<<<MROWS, 256>>>(x, g1, b1, ph);

    // 2-4. QKV projections
    dim3 g768(DIM / 128, MROWS / 128);
    mma_gemm<0><<<g768, 256, GEMM_SMEM>>>(ph, wqR, bq, nullptr, pq, DIM, DIM);
    mma_gemm<0><<<g768, 256, GEMM_SMEM>>>(ph, wkR, bk, nullptr, pk, DIM, DIM);
    mma_gemm<0><<<g768, 256, GEMM_SMEM>>>(ph, wvR, bv, nullptr, pv, DIM, DIM);

    // 5. Flash attention (launch index 5 -> ncu profiles this)
    attn_flash<<<dim3(SEQ / 64, BATCH * HEADS), 256, ATT_SMEM>>>(pq, pk, pv, adj, ph);

    // 6. Output projection + bias + residual(x) (fp32 out)
    mma_gemm<1><<<g768, 256, GEMM_SMEM>>>(ph, woR, bo, x, pout1, DIM, DIM);

    // 7. LN2 (rounded out)
    ln_kernel<<<MROWS, 256>>>(pout1, g2, b2, pq);

    // 8. FFN1 + GELU (rounded out)
    dim3 g3072(DFF / 128, MROWS / 128);
    mma_gemm<2><<<g3072, 256, GEMM_SMEM>>>(pq, w1R, bf1, nullptr, pffn, DFF, DIM);

    // 9. FFN2 + bias + residual(out1) -> final output (fp32)
    mma_gemm<1><<<g768, 256, GEMM_SMEM>>>(pffn, w2R, bf2, pout1, out, DIM, DFF);
}

// round 8
// speedup vs baseline: 6.8810x; 2.0349x over previous
#include <cuda_runtime.h>
#include <cuda_fp16.h>
#include <math.h>
#include <stdint.h>

// Problem constants
static constexpr int BATCH = 32;
static constexpr int SEQ   = 512;
static constexpr int DIM   = 768;
static constexpr int HEADS = 12;
static constexpr int HDIM  = 64;
static constexpr int MROWS = BATCH * SEQ;   // 16384
static constexpr int DFF   = 3072;

// Scratch (device globals — allocation-free rule)
__device__ __half h_ln  [MROWS * DIM];   // LN1 out (also reused for LN2 out)
__device__ __half h_q   [MROWS * DIM];
__device__ __half h_k   [MROWS * DIM];
__device__ __half h_v   [MROWS * DIM];
__device__ __half h_att [MROWS * DIM];   // attention out, [B,N,768]
__device__ __half h_gelu[MROWS * DFF];
__device__ float  g_out1[MROWS * DIM];   // attn block out (fp32, residual source)
__device__ __half h_w   [4 * DIM * DIM + 2 * DIM * DFF];  // wq,wk,wv,wo,w1,w2
__device__ unsigned long long g_mask[BATCH * SEQ * 8];    // adj bitmask

// ---------------------------------------------------------------------------
// Helpers
// ---------------------------------------------------------------------------
__device__ __forceinline__ uint32_t smem_u32(const void* p) {
    uint32_t a;
    asm("{ .reg .u64 t; cvta.to.shared.u64 t, %1; cvt.u32.u64 %0, t; }" : "=r"(a) : "l"(p));
    return a;
}
__device__ __forceinline__ uint32_t pack_h2(float a, float b) {
    __half2 t = __floats2half2_rn(a, b);
    return *reinterpret_cast<uint32_t*>(&t);
}
__device__ __forceinline__ void mma_f16(float* c, uint32_t a0, uint32_t a1,
                                        uint32_t a2, uint32_t a3,
                                        uint32_t b0, uint32_t b1) {
    asm volatile(
        "mma.sync.aligned.m16n8k16.row.col.f32.f16.f16.f32 "
        "{%0,%1,%2,%3}, {%4,%5,%6,%7}, {%8,%9}, {%0,%1,%2,%3};"
        : "+f"(c[0]), "+f"(c[1]), "+f"(c[2]), "+f"(c[3])
        : "r"(a0), "r"(a1), "r"(a2), "r"(a3), "r"(b0), "r"(b1));
}
#define LDSM4(r0, r1, r2, r3, addr)                                            \
    asm volatile("ldmatrix.sync.aligned.m8n8.x4.shared.b16 {%0,%1,%2,%3}, [%4];" \
        : "=r"(r0), "=r"(r1), "=r"(r2), "=r"(r3) : "r"(addr))
#define LDSM4T(r0, r1, r2, r3, addr)                                           \
    asm volatile("ldmatrix.sync.aligned.m8n8.x4.trans.shared.b16 {%0,%1,%2,%3}, [%4];" \
        : "=r"(r0), "=r"(r1), "=r"(r2), "=r"(r3) : "r"(addr))
#define CP_ASYNC16(dst, src) \
    asm volatile("cp.async.cg.shared.global [%0], [%1], 16;" :: "r"(dst), "l"(src))
#define CP_COMMIT()  asm volatile("cp.async.commit_group;" ::: "memory")
#define CP_WAIT(N)   asm volatile("cp.async.wait_group %0;" :: "n"(N) : "memory")

// ---------------------------------------------------------------------------
// Prep: convert all weights fp32->fp16 AND pack adj into bitmask. One launch.
// ---------------------------------------------------------------------------
static constexpr int ROUND_BLOCKS = (4 * DIM * DIM + 2 * DIM * DFF) / (256 * 8); // 3456
static constexpr int MASK_BLOCKS  = (BATCH * SEQ * 8) / 256;                     // 512

__global__ __launch_bounds__(256) void prep_kernel(
    const float* __restrict__ wq, const float* __restrict__ wk,
    const float* __restrict__ wv, const float* __restrict__ wo,
    const float* __restrict__ w1, const float* __restrict__ w2,
    const int* __restrict__ adj)
{
    int bid = blockIdx.x;
    if (bid < ROUND_BLOCKS) {
        const size_t W = (size_t)DIM * DIM;
        const size_t F = (size_t)DIM * DFF;
        size_t E = ((size_t)bid * 256 + threadIdx.x) * 8;
        const float* src; size_t off;
        if (E < 4 * W) {
            int r = (int)(E / W); off = E - (size_t)r * W;
            src = (r == 0) ? wq : (r == 1) ? wk : (r == 2) ? wv : wo;
        } else if (E < 4 * W + F) { src = w1; off = E - 4 * W; }
        else                      { src = w2; off = E - 4 * W - F; }
        float4 v0 = *(const float4*)(src + off);
        float4 v1 = *(const float4*)(src + off + 4);
        uint4 o;
        o.x = pack_h2(v0.x, v0.y); o.y = pack_h2(v0.z, v0.w);
        o.z = pack_h2(v1.x, v1.y); o.w = pack_h2(v1.z, v1.w);
        *(uint4*)(h_w + E) = o;
    } else {
        int idx = (bid - ROUND_BLOCKS) * 256 + threadIdx.x;  // row*8 + chunk
        const int* src = adj + (size_t)idx * 64;
        unsigned long long m = 0;
        #pragma unroll
        for (int i = 0; i < 16; i++) {
            int4 a = ((const int4*)src)[i];
            m |= ((unsigned long long)(a.x != 0)) << (4 * i + 0);
            m |= ((unsigned long long)(a.y != 0)) << (4 * i + 1);
            m |= ((unsigned long long)(a.z != 0)) << (4 * i + 2);
            m |= ((unsigned long long)(a.w != 0)) << (4 * i + 3);
        }
        g_mask[idx] = m;
    }
}

// ---------------------------------------------------------------------------
// fp16 mma GEMM, ldmatrix fragments, cp.async 4-stage pipeline.
// C[M,Nc] = A[M,K] @ W[K,Nc] (+epilogue). A, W are __half.
// CTA 128x128, 8 warps (4x2), warp tile 32x64, K-stage 32.
// EPI 0: +bias, permuted half store to [B,H,N,64] (feeds attention)
// EPI 1: +bias +res(fp32), fp32 store
// EPI 2: +bias, exact GELU, half store
// smem: A [4][128][40]h (pitch 80B), B [4][32][136]h (pitch 272B)
// ---------------------------------------------------------------------------
static constexpr int GST = 4;
static constexpr int A_ST = 128 * 40;    // halves per A stage (5120)
static constexpr int B_ST = 32 * 136;    // halves per B stage (4352)
static constexpr int GEMM_SMEM = GST * (A_ST + B_ST) * 2;   // 75776 B

template <int EPI>
__global__ __launch_bounds__(256, 2) void hgemm(
    const __half* __restrict__ A, const __half* __restrict__ W,
    const float* __restrict__ bias, const float* __restrict__ res,
    void* __restrict__ Cv, int Nc, int K)
{
    extern __shared__ __half hsm[];
    const uint32_t baseA = smem_u32(hsm);
    const uint32_t baseB = smem_u32(hsm + GST * A_ST);

    const int tid  = threadIdx.x;
    const int wid  = tid >> 5, lane = tid & 31;
    const int grp  = lane >> 2, tid4 = lane & 3;
    const int wm   = (wid >> 1) * 32;
    const int wn   = (wid & 1) * 64;
    const int row0 = blockIdx.y * 128;
    const int col0 = blockIdx.x * 128;

    float acc[2][8][4];
    #pragma unroll
    for (int t = 0; t < 2; t++)
        #pragma unroll
        for (int j = 0; j < 8; j++)
            #pragma unroll
            for (int r = 0; r < 4; r++) acc[t][j][r] = 0.f;

    const int nst = K >> 5;

    auto issue = [&](int s) {
        const int b = s & 3;
        const int k0 = s << 5;
        #pragma unroll
        for (int it = 0; it < 2; it++) {
            int id = tid + it * 256;
            int ar = id >> 2, ac = (id & 3) << 3;
            CP_ASYNC16(baseA + (b * A_ST + ar * 40 + ac) * 2,
                       A + (size_t)(row0 + ar) * K + k0 + ac);
            int br = id >> 4, bc = (id & 15) << 3;
            CP_ASYNC16(baseB + (b * B_ST + br * 136 + bc) * 2,
                       W + (size_t)(k0 + br) * Nc + col0 + bc);
        }
    };

    issue(0); CP_COMMIT();
    issue(1); CP_COMMIT();
    issue(2); CP_COMMIT();

    // Precomputed ldmatrix lane offsets
    const int a_row = (lane & 15), a_k8 = (lane >> 4) << 3;
    const int b_k   = (lane & 15), b_n8 = (lane >> 4) << 3;

    for (int st = 0; st < nst; st++) {
        CP_WAIT(2);
        __syncthreads();
        const uint32_t ab = baseA + (st & 3) * A_ST * 2;
        const uint32_t bb = baseB + (st & 3) * B_ST * 2;

        #pragma unroll
        for (int s = 0; s < 2; s++) {
            uint32_t af[2][4];
            #pragma unroll
            for (int t = 0; t < 2; t++) {
                uint32_t ad = ab + ((wm + t * 16 + a_row) * 40 + s * 16 + a_k8) * 2;
                LDSM4(af[t][0], af[t][1], af[t][2], af[t][3], ad);
            }
            uint32_t bfr[4][4];
            #pragma unroll
            for (int g = 0; g < 4; g++) {
                uint32_t bd = bb + ((s * 16 + b_k) * 136 + wn + g * 16 + b_n8) * 2;
                LDSM4T(bfr[g][0], bfr[g][1], bfr[g][2], bfr[g][3], bd);
            }
            #pragma unroll
            for (int t = 0; t < 2; t++)
                #pragma unroll
                for (int j = 0; j < 8; j++)
                    mma_f16(acc[t][j], af[t][0], af[t][1], af[t][2], af[t][3],
                            bfr[j >> 1][(j & 1) * 2], bfr[j >> 1][(j & 1) * 2 + 1]);
        }
        if (st + 3 < nst) issue(st + 3);
        CP_COMMIT();
    }

    // Epilogue (accum layout m16n8: rows wm+t*16+grp / +8, cols wn+j*8+tid4*2)
    #pragma unroll
    for (int t = 0; t < 2; t++) {
        int r_lo = row0 + wm + t * 16 + grp;
        int r_hi = r_lo + 8;
        #pragma unroll
        for (int j = 0; j < 8; j++) {
            int c = col0 + wn + j * 8 + tid4 * 2;
            float b0 = bias[c], b1 = bias[c + 1];
            float v00 = acc[t][j][0] + b0, v01 = acc[t][j][1] + b1;
            float v10 = acc[t][j][2] + b0, v11 = acc[t][j][3] + b1;
            if (EPI == 0) {
                __half* C = (__half*)Cv;
                int h = c >> 6, d = c & 63;
                int blo = r_lo >> 9, nlo = r_lo & 511;
                int bhi = r_hi >> 9, nhi = r_hi & 511;
                *(__half2*)(C + (((size_t)(blo * HEADS + h)) * SEQ + nlo) * HDIM + d) =
                    __floats2half2_rn(v00, v01);
                *(__half2*)(C + (((size_t)(bhi * HEADS + h)) * SEQ + nhi) * HDIM + d) =
                    __floats2half2_rn(v10, v11);
            } else if (EPI == 1) {
                float* C = (float*)Cv;
                const float2 r0 = *(const float2*)(res + (size_t)r_lo * Nc + c);
                const float2 r1 = *(const float2*)(res + (size_t)r_hi * Nc + c);
                *(float2*)(C + (size_t)r_lo * Nc + c) = make_float2(v00 + r0.x, v01 + r0.y);
                *(float2*)(C + (size_t)r_hi * Nc + c) = make_float2(v10 + r1.x, v11 + r1.y);
            } else {
                __half* C = (__half*)Cv;
                const float is2 = 0.70710678118654752f;
                v00 = 0.5f * v00 * (1.0f + erff(v00 * is2));
                v01 = 0.5f * v01 * (1.0f + erff(v01 * is2));
                v10 = 0.5f * v10 * (1.0f + erff(v10 * is2));
                v11 = 0.5f * v11 * (1.0f + erff(v11 * is2));
                *(__half2*)(C + (size_t)r_lo * Nc + c) = __floats2half2_rn(v00, v01);
                *(__half2*)(C + (size_t)r_hi * Nc + c) = __floats2half2_rn(v10, v11);
            }
        }
    }
}

// ---------------------------------------------------------------------------
// LayerNorm: fp32 in -> half out
// ---------------------------------------------------------------------------
__global__ __launch_bounds__(256) void ln_kernel(
    const float* __restrict__ x, const float* __restrict__ g,
    const float* __restrict__ b, __half* __restrict__ y)
{
    int row = blockIdx.x;
    int tid = threadIdx.x;
    const float* xr = x + (size_t)row * DIM;
    float v0 = xr[tid], v1 = xr[tid + 256], v2 = xr[tid + 512];
    float s  = v0 + v1 + v2;
    float ss = v0 * v0 + v1 * v1 + v2 * v2;
    #pragma unroll
    for (int o = 16; o > 0; o >>= 1) {
        s  += __shfl_xor_sync(0xffffffffu, s, o);
        ss += __shfl_xor_sync(0xffffffffu, ss, o);
    }
    __shared__ float sh_s[8], sh_ss[8];
    int w = tid >> 5, l = tid & 31;
    if (l == 0) { sh_s[w] = s; sh_ss[w] = ss; }
    __syncthreads();
    float ts = 0.f, tss = 0.f;
    #pragma unroll
    for (int i = 0; i < 8; i++) { ts += sh_s[i]; tss += sh_ss[i]; }
    float mean = ts * (1.0f / DIM);
    float var  = tss * (1.0f / DIM) - mean * mean;
    float inv  = rsqrtf(var + 1e-5f);
    __half* yr = y + (size_t)row * DIM;
    yr[tid]       = __float2half_rn((v0 - mean) * inv * g[tid]       + b[tid]);
    yr[tid + 256] = __float2half_rn((v1 - mean) * inv * g[tid + 256] + b[tid + 256]);
    yr[tid + 512] = __float2half_rn((v2 - mean) * inv * g[tid + 512] + b[tid + 512]);
}

// ---------------------------------------------------------------------------
// Flash attention, fp16 mma + ldmatrix, warp-local softmax, in-register P.
// Grid (SEQ/128, B*H), 256 threads; warp w owns q-rows [w*16, w*16+16).
// Smem: Q[128][72]h, K 2x[64][72]h, V 2x[64][72]h  (55296 B)
// ---------------------------------------------------------------------------
static constexpr int QP   = 72;                     // half pitch (144 B)
static constexpr int O_Q  = 0;
static constexpr int O_K  = 128 * QP;               // 9216 halves
static constexpr int O_V  = O_K + 2 * 64 * QP;      // + 9216
static constexpr int ATT_SMEM = (O_V + 2 * 64 * QP) * 2;   // 55296 B

__global__ __launch_bounds__(256, 2) void attn_flash(
    const __half* __restrict__ q, const __half* __restrict__ kin,
    const __half* __restrict__ v, const unsigned long long* __restrict__ mask,
    __half* __restrict__ out)
{
    extern __shared__ __half hsm[];
    const uint32_t baseQ = smem_u32(hsm + O_Q);
    const uint32_t baseK = smem_u32(hsm + O_K);
    const uint32_t baseV = smem_u32(hsm + O_V);

    const int tid  = threadIdx.x;
    const int wid  = tid >> 5, lane = tid & 31;
    const int grp  = lane >> 2, tid4 = lane & 3;
    const int m0   = wid * 16;
    const int bh   = blockIdx.y;
    const int bb   = bh / HEADS, hh = bh % HEADS;
    const int q0   = blockIdx.x * 128;

    const __half* qb = q   + (size_t)bh * SEQ * HDIM + (size_t)q0 * HDIM;
    const __half* kb = kin + (size_t)bh * SEQ * HDIM;
    const __half* vb = v   + (size_t)bh * SEQ * HDIM;

    // Stage Q (128x64h): 4 chunks/thread
    #pragma unroll
    for (int it = 0; it < 4; it++) {
        int id = tid + it * 256;
        int r = id >> 3, c = (id & 7) << 3;
        CP_ASYNC16(baseQ + (r * QP + c) * 2, qb + r * HDIM + c);
    }
    // Stage K0, V0 (64x64h each): 2 chunks/thread
    #pragma unroll
    for (int it = 0; it < 2; it++) {
        int id = tid + it * 256;
        int r = id >> 3, c = (id & 7) << 3;
        CP_ASYNC16(baseK + (r * QP + c) * 2, kb + r * HDIM + c);
        CP_ASYNC16(baseV + (r * QP + c) * 2, vb + r * HDIM + c);
    }
    CP_COMMIT();

    float m_run0 = -1e30f, m_run1 = -1e30f;
    float l_run0 = 0.f,    l_run1 = 0.f;
    float acc[8][4];
    #pragma unroll
    for (int j = 0; j < 8; j++)
        #pragma unroll
        for (int r = 0; r < 4; r++) acc[j][r] = 0.f;

    uint32_t qf[4][4];
    const float scale = 0.125f;

    // ldmatrix lane offsets
    const int l15 = lane & 15, l7 = lane & 7;
    const int hi8 = (lane >> 4) << 3;          // 0 or 8 (x4 block col select)
    const int b8  = ((lane >> 3) & 1) << 3;    // 0 or 8

    for (int kt = 0; kt < 8; kt++) {
        CP_WAIT(0);
        __syncthreads();
        if (kt + 1 < 8) {
            int bufn = ((kt + 1) & 1) * 64 * QP * 2;
            const __half* kn = kb + (size_t)(kt + 1) * 64 * HDIM;
            const __half* vn = vb + (size_t)(kt + 1) * 64 * HDIM;
            #pragma unroll
            for (int it = 0; it < 2; it++) {
                int id = tid + it * 256;
                int r = id >> 3, c = (id & 7) << 3;
                CP_ASYNC16(baseK + bufn + (r * QP + c) * 2, kn + r * HDIM + c);
                CP_ASYNC16(baseV + bufn + (r * QP + c) * 2, vn + r * HDIM + c);
            }
        }
        CP_COMMIT();

        if (kt == 0) {
            #pragma unroll
            for (int ks = 0; ks < 4; ks++) {
                uint32_t ad = baseQ + ((m0 + l15) * QP + ks * 16 + hi8) * 2;
                LDSM4(qf[ks][0], qf[ks][1], qf[ks][2], qf[ks][3], ad);
            }
        }

        const uint32_t kbuf = baseK + (kt & 1) * 64 * QP * 2;
        const uint32_t vbuf = baseV + (kt & 1) * 64 * QP * 2;

        // ---- scores: m16 x n64 ----
        float sc[8][4];
        #pragma unroll
        for (int j = 0; j < 8; j++)
            #pragma unroll
            for (int r = 0; r < 4; r++) sc[j][r] = 0.f;

        #pragma unroll
        for (int ks = 0; ks < 4; ks++) {
            #pragma unroll
            for (int g = 0; g < 4; g++) {
                // K stored [key][dim]; non-trans gives B frags directly
                uint32_t kd = kbuf + ((g * 16 + l7 + hi8) * QP + ks * 16 + b8) * 2;
                uint32_t k0r, k1r, k2r, k3r;
                LDSM4(k0r, k1r, k2r, k3r, kd);
                mma_f16(sc[2 * g],     qf[ks][0], qf[ks][1], qf[ks][2], qf[ks][3], k0r, k1r);
                mma_f16(sc[2 * g + 1], qf[ks][0], qf[ks][1], qf[ks][2], qf[ks][3], k2r, k3r);
            }
        }

        // ---- mask + online softmax (warp-local, quad reduce) ----
        unsigned long long mlo = mask[((size_t)bb * SEQ + q0 + m0 + grp)     * 8 + kt];
        unsigned long long mhi = mask[((size_t)bb * SEQ + q0 + m0 + grp + 8) * 8 + kt];
        float mx0 = -1e30f, mx1 = -1e30f;
        #pragma unroll
        for (int j = 0; j < 8; j++) {
            int c0 = j * 8 + tid4 * 2;
            sc[j][0] = ((mlo >> c0) & 1)       ? sc[j][0] * scale : -1e30f;
            sc[j][1] = ((mlo >> (c0 + 1)) & 1) ? sc[j][1] * scale : -1e30f;
            sc[j][2] = ((mhi >> c0) & 1)       ? sc[j][2] * scale : -1e30f;
            sc[j][3] = ((mhi >> (c0 + 1)) & 1) ? sc[j][3] * scale : -1e30f;
            mx0 = fmaxf(mx0, fmaxf(sc[j][0], sc[j][1]));
            mx1 = fmaxf(mx1, fmaxf(sc[j][2], sc[j][3]));
        }
        mx0 = fmaxf(mx0, __shfl_xor_sync(0xffffffffu, mx0, 1));
        mx0 = fmaxf(mx0, __shfl_xor_sync(0xffffffffu, mx0, 2));
        mx1 = fmaxf(mx1, __shfl_xor_sync(0xffffffffu, mx1, 1));
        mx1 = fmaxf(mx1, __shfl_xor_sync(0xffffffffu, mx1, 2));

        float mn0 = fmaxf(m_run0, mx0), mn1 = fmaxf(m_run1, mx1);
        float f0 = __expf(m_run0 - mn0), f1 = __expf(m_run1 - mn1);
        m_run0 = mn0; m_run1 = mn1;

        float s0 = 0.f, s1 = 0.f;
        uint32_t pl[8], ph[8];
        #pragma unroll
        for (int j = 0; j < 8; j++) {
            float e0 = (sc[j][0] > -1e29f) ? __expf(sc[j][0] - mn0) : 0.f;
            float e1 = (sc[j][1] > -1e29f) ? __expf(sc[j][1] - mn0) : 0.f;
            float e2 = (sc[j][2] > -1e29f) ? __expf(sc[j][2] - mn1) : 0.f;
            float e3 = (sc[j][3] > -1e29f) ? __expf(sc[j][3] - mn1) : 0.f;
            s0 += e0 + e1; s1 += e2 + e3;
            pl[j] = pack_h2(e0, e1);
            ph[j] = pack_h2(e2, e3);
        }
        s0 += __shfl_xor_sync(0xffffffffu, s0, 1);
        s0 += __shfl_xor_sync(0xffffffffu, s0, 2);
        s1 += __shfl_xor_sync(0xffffffffu, s1, 1);
        s1 += __shfl_xor_sync(0xffffffffu, s1, 2);
        l_run0 = l_run0 * f0 + s0;
        l_run1 = l_run1 * f1 + s1;

        #pragma unroll
        for (int j = 0; j < 8; j++) {
            acc[j][0] *= f0; acc[j][1] *= f0;
            acc[j][2] *= f1; acc[j][3] *= f1;
        }

        // ---- P @ V (P frags in registers; V trans ldmatrix) ----
        #pragma unroll
        for (int s = 0; s < 4; s++) {
            uint32_t a0 = pl[2 * s], a1 = ph[2 * s], a2 = pl[2 * s + 1], a3 = ph[2 * s + 1];
            #pragma unroll
            for (int g = 0; g < 4; g++) {
                uint32_t vd = vbuf + ((s * 16 + l15) * QP + g * 16 + hi8) * 2;
                uint32_t v0r, v1r, v2r, v3r;
                LDSM4T(v0r, v1r, v2r, v3r, vd);
                mma_f16(acc[2 * g],     a0, a1, a2, a3, v0r, v1r);
                mma_f16(acc[2 * g + 1], a0, a1, a2, a3, v2r, v3r);
            }
        }
    }

    // ---- finalize ----
    const float inv0 = 1.0f / l_run0;
    const float inv1 = 1.0f / l_run1;
    const int rlo = q0 + m0 + grp, rhi = rlo + 8;
    #pragma unroll
    for (int j = 0; j < 8; j++) {
        int d = hh * HDIM + j * 8 + tid4 * 2;
        *(__half2*)(out + ((size_t)bb * SEQ + rlo) * DIM + d) =
            __floats2half2_rn(acc[j][0] * inv0, acc[j][1] * inv0);
        *(__half2*)(out + ((size_t)bb * SEQ + rhi) * DIM + d) =
            __floats2half2_rn(acc[j][2] * inv1, acc[j][3] * inv1);
    }
}

// ---------------------------------------------------------------------------
extern "C" void kernel_launch(void* const* d_in, const int* in_sizes, int n_in,
                              void* d_out, int out_size)
{
    const float* x   = (const float*)d_in[0];
    const int*   adj = (const int*)  d_in[1];
    const float* wq  = (const float*)d_in[2];
    const float* bq  = (const float*)d_in[3];
    const float* wk  = (const float*)d_in[4];
    const float* bk  = (const float*)d_in[5];
    const float* wv  = (const float*)d_in[6];
    const float* bv  = (const float*)d_in[7];
    const float* wo  = (const float*)d_in[8];
    const float* bo  = (const float*)d_in[9];
    const float* g1  = (const float*)d_in[10];
    const float* b1  = (const float*)d_in[11];
    const float* g2  = (const float*)d_in[12];
    const float* b2  = (const float*)d_in[13];
    const float* w1  = (const float*)d_in[14];
    const float* bf1 = (const float*)d_in[15];
    const float* w2  = (const float*)d_in[16];
    const float* bf2 = (const float*)d_in[17];
    float* out = (float*)d_out;

    __half *pln, *pq, *pk, *pv, *patt, *pgelu, *pw;
    float  *pout1;
    unsigned long long* pmask;
    cudaGetSymbolAddress((void**)&pln,   h_ln);
    cudaGetSymbolAddress((void**)&pq,    h_q);
    cudaGetSymbolAddress((void**)&pk,    h_k);
    cudaGetSymbolAddress((void**)&pv,    h_v);
    cudaGetSymbolAddress((void**)&patt,  h_att);
    cudaGetSymbolAddress((void**)&pgelu, h_gelu);
    cudaGetSymbolAddress((void**)&pw,    h_w);
    cudaGetSymbolAddress((void**)&pout1, g_out1);
    cudaGetSymbolAddress((void**)&pmask, g_mask);

    __half* wqH = pw;
    __half* wkH = pw + DIM * DIM;
    __half* wvH = pw + 2 * DIM * DIM;
    __half* woH = pw + 3 * DIM * DIM;
    __half* w1H = pw + 4 * DIM * DIM;
    __half* w2H = pw + 4 * DIM * DIM + DIM * DFF;

    static bool attr_set = false;
    if (!attr_set) {
        cudaFuncSetAttribute(attn_flash, cudaFuncAttributeMaxDynamicSharedMemorySize, ATT_SMEM);
        cudaFuncSetAttribute(hgemm<0>, cudaFuncAttributeMaxDynamicSharedMemorySize, GEMM_SMEM);
        cudaFuncSetAttribute(hgemm<1>, cudaFuncAttributeMaxDynamicSharedMemorySize, GEMM_SMEM);
        cudaFuncSetAttribute(hgemm<2>, cudaFuncAttributeMaxDynamicSharedMemorySize, GEMM_SMEM);
        attr_set = true;
    }

    // 0. Prep: weights->fp16 + adj bitmask (single launch)
    prep_kernel<<<ROUND_BLOCKS + MASK_BLOCKS, 256>>>(wq, wk, wv, wo, w1, w2, adj);

    // 1. LN1 -> half
    ln_kernel<<<MROWS, 256>>>(x, g1, b1, pln);

    // 2-4. QKV projections (half in/out, permuted epilogue)
    dim3 g768(DIM / 128, MROWS / 128);
    hgemm<0><<<g768, 256, GEMM_SMEM>>>(pln, wqH, bq, nullptr, pq, DIM, DIM);
    hgemm<0><<<g768, 256, GEMM_SMEM>>>(pln, wkH, bk, nullptr, pk, DIM, DIM);
    hgemm<0><<<g768, 256, GEMM_SMEM>>>(pln, wvH, bv, nullptr, pv, DIM, DIM);

    // 5. Flash attention (launch idx 5 -> ncu target), half out [B,N,768]
    attn_flash<<<dim3(SEQ / 128, BATCH * HEADS), 256, ATT_SMEM>>>(pq, pk, pv, pmask, patt);

    // 6. Output projection + bias + residual(x) -> fp32 out1
    hgemm<1><<<g768, 256, GEMM_SMEM>>>(patt, woH, bo, x, pout1, DIM, DIM);

    // 7. LN2 -> half (reuse h_ln)
    ln_kernel<<<MROWS, 256>>>(pout1, g2, b2, pln);

    // 8. FFN1 + GELU -> half
    dim3 g3072(DFF / 128, MROWS / 128);
    hgemm<2><<<g3072, 256, GEMM_SMEM>>>(pln, w1H, bf1, nullptr, pgelu, DFF, DIM);

    // 9. FFN2 + bias + residual(out1) -> final fp32 output
    hgemm<1><<<g768, 256, GEMM_SMEM>>>(pgelu, w2H, bf2, pout1, out, DIM, DFF);
}